// round 14
// baseline (speedup 1.0000x reference)
#include <cuda_runtime.h>
#include <cuda_bf16.h>
#include <math.h>
#include <stdint.h>

// ---------------- problem constants ----------------
#define NB 5
#define SEQ 1024
#define T 1025
#define DM 512
#define NHEAD 8
#define HD 64
#define DFF 2048
#define NL 4
#define NTOK 51
#define MLPD 256
#define CLASSES 7
#define GH 3
#define GHID 64
#define GCLS 5
#define MROWS (NB * T)
#define NBLK 41
#define GAT_GRAPHS (SEQ * 5)
#define OUT_GAT_BASE (NB * CLASSES)
#define NWIN 17
#define KV_PER_HEAD (NWIN * 4096)

// ---------------- scratch ----------------
__device__ float g_h [MROWS * DM];
__device__ float g_q [MROWS * DM];
__device__ float g_t [MROWS * DM];
// fragment-packed activations (zero-init tails)
__device__ float g_hF [NBLK * 128 * DM];
__device__ float g_ffF[NBLK * 128 * DFF];
__device__ float g_aoF[NBLK * 128 * DM];
// fragment-packed (tf32-rounded) weights
__device__ float g_WqF[NL * DM * DM];
__device__ float g_WkF[NL * DM * DM];
__device__ float g_WvF[NL * DM * DM];
__device__ float g_WoF[NL * DM * DM];
__device__ float g_W1F[NL * DM * DFF];
__device__ float g_W2F[NL * DFF * DM];
// fragment-packed K / V(hi,lo)  (invalid keys stay zero from static init)
__device__ float g_kF  [NB * NHEAD * KV_PER_HEAD];
__device__ float g_vhiF[NB * NHEAD * KV_PER_HEAD];
__device__ float g_vloF[NB * NHEAD * KV_PER_HEAD];

// ---------------- helpers ----------------
__device__ __forceinline__ uint32_t ftf32(float x) {
    uint32_t r;
    asm("cvt.rna.tf32.f32 %0, %1;" : "=r"(r) : "f"(x));
    return r;
}

#define MMA_TF32(d, a, b) \
    asm volatile("mma.sync.aligned.m16n8k8.row.col.f32.tf32.tf32.f32 " \
        "{%0,%1,%2,%3}, {%4,%5,%6,%7}, {%8,%9}, {%0,%1,%2,%3};" \
        : "+f"((d)[0]), "+f"((d)[1]), "+f"((d)[2]), "+f"((d)[3]) \
        : "r"((a).x), "r"((a).y), "r"((a).z), "r"((a).w), \
          "r"((b).x), "r"((b).y))

#define MMA_TF32_P(d, a0, a1, a2, a3, b) \
    asm volatile("mma.sync.aligned.m16n8k8.row.col.f32.tf32.tf32.f32 " \
        "{%0,%1,%2,%3}, {%4,%5,%6,%7}, {%8,%9}, {%0,%1,%2,%3};" \
        : "+f"((d)[0]), "+f"((d)[1]), "+f"((d)[2]), "+f"((d)[3]) \
        : "r"(a0), "r"(a1), "r"(a2), "r"(a3), \
          "r"((b).x), "r"((b).y))

// store value into A-fragment layout (per 128-row block, width Ncols)
__device__ __forceinline__ void store_frag(float* F, int Ncols, int row, int col, float val) {
    size_t slot = (size_t)(row >> 7) * 128 * Ncols
        + (size_t)((col >> 3) * 8 + ((row & 127) >> 4)) * 128
        + ((row & 7) * 4 + (col & 3)) * 4
        + (((col & 7) >= 4) ? 2 : 0) + ((row >> 3) & 1);
    F[slot] = __uint_as_float(ftf32(val));
}

// ---------------- weight -> B-fragment packing ----------------
__global__ __launch_bounds__(256) void frag_all(
    const float* __restrict__ Wq, const float* __restrict__ Wk,
    const float* __restrict__ Wv, const float* __restrict__ Wo,
    const float* __restrict__ W1, const float* __restrict__ W2,
    float* __restrict__ WqF, float* __restrict__ WkF,
    float* __restrict__ WvF, float* __restrict__ WoF,
    float* __restrict__ W1F, float* __restrict__ W2F)
{
    __shared__ float t[32][33];
    int bid = blockIdx.x;
    const float* W; float* Wf; int K, N, rel, nx;
    if (bid < 4096) {
        int job = bid >> 10; rel = bid & 1023;
        K = DM; N = DM; nx = 16;
        if (job == 0)      { W = Wq; Wf = WqF; }
        else if (job == 1) { W = Wk; Wf = WkF; }
        else if (job == 2) { W = Wv; Wf = WvF; }
        else               { W = Wo; Wf = WoF; }
    } else if (bid < 8192) {
        rel = bid - 4096; K = DM; N = DFF; nx = 64;
        W = W1; Wf = W1F;
    } else {
        rel = bid - 8192; K = DFF; N = DM; nx = 16;
        W = W2; Wf = W2F;
    }
    int ny = K >> 5;
    int per = nx * ny;
    int l = rel / per, r2 = rel % per;
    int n0 = (r2 % nx) * 32, k0 = (r2 / nx) * 32;
    const float* w = W + (size_t)l * K * N;
    float* o = Wf + (size_t)l * K * N;
    int tx = threadIdx.x & 31, ty = threadIdx.x >> 5;
    #pragma unroll
    for (int i = 0; i < 32; i += 8)
        t[ty + i][tx] = w[(size_t)(k0 + ty + i) * N + n0 + tx];
    __syncthreads();
    int Kt = K >> 3;
    #pragma unroll
    for (int it = 0; it < 4; it++) {
        int w2 = threadIdx.x + it * 256;
        int group = w2 >> 6, within = w2 & 63;
        int ktl = group & 3, ntl = group >> 2;
        int lane = within >> 1, r = within & 1;
        int kk = ktl * 8 + (lane & 3) + r * 4;
        int nn = ntl * 8 + (lane >> 2);
        o[((size_t)((n0 >> 3) + ntl) * Kt + (k0 >> 3) + ktl) * 64 + within]
            = __uint_as_float(ftf32(t[kk][nn]));
    }
}

// ---------------- frag-A GEMM: 128x64 CTA tile, 64x16 warp tile, B-prefetch x2 ----------------
__device__ __forceinline__ void mma_gemm_fA_body(
    const float* __restrict__ Af, const float* __restrict__ Bf,
    const float* __restrict__ bias, float* __restrict__ C,
    float* __restrict__ Cf, int M, int N, int K, int relu)
{
    int tid = threadIdx.x;
    int w = tid >> 5, lane = tid & 31;
    int bm = blockIdx.y * 128, bn = blockIdx.x * 64;
    int wm = (w & 1) * 64, wn = (w >> 1) * 16;
    int Kt = K >> 3;
    int nt0 = (bn + wn) >> 3;
    int mtw = wm >> 4;
    const float* Ab = Af + (size_t)blockIdx.y * 128 * K;

    float d[4][2][4];
    #pragma unroll
    for (int i = 0; i < 4; i++)
        #pragma unroll
        for (int j = 0; j < 2; j++)
            #pragma unroll
            for (int e = 0; e < 4; e++) d[i][j][e] = 0.f;

    uint4 ac[4];
    uint2 b0[2], b1[2], b2v[2];
    #pragma unroll
    for (int i = 0; i < 4; i++)
        ac[i] = *(const uint4*)(Ab + ((mtw + i) * 32 + lane) * 4);
    #pragma unroll
    for (int j = 0; j < 2; j++) {
        b0[j] = *(const uint2*)(Bf + ((size_t)(nt0 + j) * Kt) * 64 + lane * 2);
        b1[j] = *(const uint2*)(Bf + ((size_t)(nt0 + j) * Kt + 1) * 64 + lane * 2);
    }

    for (int ktg = 0; ktg < Kt; ktg++) {
        if (ktg + 2 < Kt) {
            #pragma unroll
            for (int j = 0; j < 2; j++)
                b2v[j] = *(const uint2*)(Bf + ((size_t)(nt0 + j) * Kt + ktg + 2) * 64 + lane * 2);
        }
        #pragma unroll
        for (int i = 0; i < 4; i++)
            #pragma unroll
            for (int j = 0; j < 2; j++)
                MMA_TF32(d[i][j], ac[i], b0[j]);
        if (ktg + 1 < Kt) {
            #pragma unroll
            for (int i = 0; i < 4; i++)
                ac[i] = *(const uint4*)(Ab + (((ktg + 1) * 8 + mtw + i) * 32 + lane) * 4);
            #pragma unroll
            for (int j = 0; j < 2; j++) { b0[j] = b1[j]; b1[j] = b2v[j]; }
        }
    }

    int g = lane >> 2, t2 = (lane & 3) << 1;
    if (Cf) {
        size_t cb = (size_t)blockIdx.y * 128 * N;
        #pragma unroll
        for (int i = 0; i < 4; i++)
            #pragma unroll
            for (int hh = 0; hh < 2; hh++) {
                int rloc = wm + i * 16 + g + hh * 8;
                #pragma unroll
                for (int j = 0; j < 2; j++)
                    #pragma unroll
                    for (int e = 0; e < 2; e++) {
                        int col = bn + wn + j * 8 + t2 + e;
                        float val = d[i][j][hh * 2 + e] + bias[col];
                        if (relu) val = fmaxf(val, 0.f);
                        size_t slot = cb + (size_t)((col >> 3) * 8 + (rloc >> 4)) * 128
                                      + ((rloc & 7) * 4 + (col & 3)) * 4
                                      + (((col & 7) >= 4) ? 2 : 0) + hh;
                        Cf[slot] = __uint_as_float(ftf32(val));
                    }
            }
    } else {
        #pragma unroll
        for (int i = 0; i < 4; i++) {
            #pragma unroll
            for (int hh = 0; hh < 2; hh++) {
                int row = bm + wm + i * 16 + g + hh * 8;
                if (row >= M) continue;
                #pragma unroll
                for (int j = 0; j < 2; j++) {
                    int col = bn + wn + j * 8 + t2;
                    float2 bb = *(const float2*)(bias + col);
                    float2 r;
                    r.x = d[i][j][hh * 2 + 0] + bb.x;
                    r.y = d[i][j][hh * 2 + 1] + bb.y;
                    if (relu) { r.x = fmaxf(r.x, 0.f); r.y = fmaxf(r.y, 0.f); }
                    *(float2*)(C + (size_t)row * N + col) = r;
                }
            }
        }
    }
}

__global__ __launch_bounds__(256, 3) void mma_gemm_fA(
    const float* __restrict__ Af, const float* __restrict__ Bf,
    const float* __restrict__ bias, float* __restrict__ C,
    float* __restrict__ Cf, int M, int N, int K, int relu)
{
    mma_gemm_fA_body(Af, Bf, bias, C, Cf, M, N, K, relu);
}

// ---------------- qkv GEMM: Q -> row-major, K/V -> KV fragment layouts ----------------
__global__ __launch_bounds__(256, 3) void mma_gemm_qkv_fA(
    const float* __restrict__ Af,
    const float* __restrict__ WqF, const float* __restrict__ WkF, const float* __restrict__ WvF,
    const float* __restrict__ bq, const float* __restrict__ bk, const float* __restrict__ bv,
    float* __restrict__ q,
    float* __restrict__ kF, float* __restrict__ vhiF, float* __restrict__ vloF)
{
    const float* Bf; const float* bias;
    if (blockIdx.z == 0)      { Bf = WqF; bias = bq; }
    else if (blockIdx.z == 1) { Bf = WkF; bias = bk; }
    else                      { Bf = WvF; bias = bv; }

    int tid = threadIdx.x;
    int w = tid >> 5, lane = tid & 31;
    int bm = blockIdx.y * 128, bn = blockIdx.x * 64;
    int wm = (w & 1) * 64, wn = (w >> 1) * 16;
    int Kt = DM >> 3;
    int nt0 = (bn + wn) >> 3;
    int mtw = wm >> 4;
    const float* Ab = Af + (size_t)blockIdx.y * 128 * DM;

    float d[4][2][4];
    #pragma unroll
    for (int i = 0; i < 4; i++)
        #pragma unroll
        for (int j = 0; j < 2; j++)
            #pragma unroll
            for (int e = 0; e < 4; e++) d[i][j][e] = 0.f;

    uint4 ac[4];
    uint2 b0[2], b1[2], b2v[2];
    #pragma unroll
    for (int i = 0; i < 4; i++)
        ac[i] = *(const uint4*)(Ab + ((mtw + i) * 32 + lane) * 4);
    #pragma unroll
    for (int j = 0; j < 2; j++) {
        b0[j] = *(const uint2*)(Bf + ((size_t)(nt0 + j) * Kt) * 64 + lane * 2);
        b1[j] = *(const uint2*)(Bf + ((size_t)(nt0 + j) * Kt + 1) * 64 + lane * 2);
    }

    for (int ktg = 0; ktg < Kt; ktg++) {
        if (ktg + 2 < Kt) {
            #pragma unroll
            for (int j = 0; j < 2; j++)
                b2v[j] = *(const uint2*)(Bf + ((size_t)(nt0 + j) * Kt + ktg + 2) * 64 + lane * 2);
        }
        #pragma unroll
        for (int i = 0; i < 4; i++)
            #pragma unroll
            for (int j = 0; j < 2; j++)
                MMA_TF32(d[i][j], ac[i], b0[j]);
        if (ktg + 1 < Kt) {
            #pragma unroll
            for (int i = 0; i < 4; i++)
                ac[i] = *(const uint4*)(Ab + (((ktg + 1) * 8 + mtw + i) * 32 + lane) * 4);
            #pragma unroll
            for (int j = 0; j < 2; j++) { b0[j] = b1[j]; b1[j] = b2v[j]; }
        }
    }

    int g = lane >> 2, t2 = (lane & 3) << 1;
    if (blockIdx.z == 0) {
        #pragma unroll
        for (int i = 0; i < 4; i++) {
            #pragma unroll
            for (int hh = 0; hh < 2; hh++) {
                int row = bm + wm + i * 16 + g + hh * 8;
                if (row >= MROWS) continue;
                #pragma unroll
                for (int j = 0; j < 2; j++) {
                    int col = bn + wn + j * 8 + t2;
                    float2 bb = *(const float2*)(bias + col);
                    float2 r;
                    r.x = d[i][j][hh * 2 + 0] + bb.x;
                    r.y = d[i][j][hh * 2 + 1] + bb.y;
                    *(float2*)(q + (size_t)row * DM + col) = r;
                }
            }
        }
    } else {
        int isK = (blockIdx.z == 1);
        #pragma unroll
        for (int i = 0; i < 4; i++) {
            #pragma unroll
            for (int hh = 0; hh < 2; hh++) {
                int row = bm + wm + i * 16 + g + hh * 8;
                if (row >= MROWS) continue;
                int b = row / T, t = row % T;
                int win = t >> 6, key = t & 63;
                #pragma unroll
                for (int j = 0; j < 2; j++) {
                    #pragma unroll
                    for (int e = 0; e < 2; e++) {
                        int col = bn + wn + j * 8 + t2 + e;
                        float val = d[i][j][hh * 2 + e] + bias[col];
                        int head = col >> 6, dd = col & 63;
                        size_t base = (((size_t)(b * NHEAD + head) * NWIN + win)) * 4096;
                        if (isK) {
                            kF[base + ((dd >> 3) * 8 + (key >> 3)) * 64
                               + ((key & 7) * 4 + (dd & 3)) * 2 + ((dd & 7) >> 2)]
                                = __uint_as_float(ftf32(val));
                        } else {
                            uint32_t hb = ftf32(val);
                            float hf = __uint_as_float(hb);
                            uint32_t lb = ftf32(val - hf);
                            size_t a2 = base + ((key >> 3) * 8 + (dd >> 3)) * 64
                                        + ((dd & 7) * 4 + (key & 3)) * 2 + ((key & 7) >> 2);
                            vhiF[a2] = __uint_as_float(hb);
                            vloF[a2] = __uint_as_float(lb);
                        }
                    }
                }
            }
        }
    }
}

// ---------------- tf32 mma.sync flash attention -> frag output ----------------
#define ATT_SMEM 65536

__global__ __launch_bounds__(256) void attn_mma_kernel(
    const float* __restrict__ q,
    const float* __restrict__ kF, const float* __restrict__ vhiF,
    const float* __restrict__ vloF, float* __restrict__ aoF)
{
    extern __shared__ float as_[];
    float* kp  = as_;
    float* vhi = as_ + 8192;
    float* vlo = as_ + 12288;

    int tid = threadIdx.x;
    int w = tid >> 5, lane = tid & 31;
    int g = lane >> 2, t = lane & 3;
    int qb = blockIdx.x * 128;
    int head = blockIdx.y, b = blockIdx.z;
    int bh = b * NHEAD + head;
    const float* qp = q + (size_t)b * T * DM + head * HD;
    const float* kFb = kF   + (size_t)bh * KV_PER_HEAD;
    const float* vhb = vhiF + (size_t)bh * KV_PER_HEAD;
    const float* vlb = vloF + (size_t)bh * KV_PER_HEAD;

    int r0 = qb + w * 16 + g;
    int r1 = r0 + 8;
    uint32_t aq[8][4];
    #pragma unroll
    for (int kk = 0; kk < 8; kk++) {
        int d0 = kk * 8 + t, d1 = d0 + 4;
        float q00 = 0.f, q01 = 0.f, q10 = 0.f, q11 = 0.f;
        if (r0 < T) { q00 = qp[(size_t)r0 * DM + d0]; q01 = qp[(size_t)r0 * DM + d1]; }
        if (r1 < T) { q10 = qp[(size_t)r1 * DM + d0]; q11 = qp[(size_t)r1 * DM + d1]; }
        aq[kk][0] = ftf32(q00 * 0.125f);
        aq[kk][1] = ftf32(q10 * 0.125f);
        aq[kk][2] = ftf32(q01 * 0.125f);
        aq[kk][3] = ftf32(q11 * 0.125f);
    }

    float oc[8][4];
    #pragma unroll
    for (int j = 0; j < 8; j++)
        #pragma unroll
        for (int e = 0; e < 4; e++) oc[j][e] = 0.f;
    float m0 = -1e30f, m1 = -1e30f, l0 = 0.f, l1 = 0.f;

    for (int win = 0; win < NWIN; win++) {
        int kb = win * 64;
        __syncthreads();
        {
            const float4* ks = (const float4*)(kFb + (size_t)win * 4096);
            const float4* hs = (const float4*)(vhb + (size_t)win * 4096);
            const float4* ls = (const float4*)(vlb + (size_t)win * 4096);
            float4* kd = (float4*)kp;
            float4* hd = (float4*)vhi;
            float4* ld = (float4*)vlo;
            #pragma unroll
            for (int i = 0; i < 4; i++) {
                int idx = tid + i * 256;
                kd[idx] = ks[idx];
                hd[idx] = hs[idx];
                ld[idx] = ls[idx];
            }
        }
        __syncthreads();

        float sc[8][4];
        #pragma unroll
        for (int j = 0; j < 8; j++)
            #pragma unroll
            for (int e = 0; e < 4; e++) sc[j][e] = 0.f;
        #pragma unroll
        for (int kk = 0; kk < 8; kk++) {
            #pragma unroll
            for (int j = 0; j < 8; j++) {
                uint2 bf = *(const uint2*)&kp[(kk * 8 + j) * 64 + lane * 2];
                MMA_TF32_P(sc[j], aq[kk][0], aq[kk][1], aq[kk][2], aq[kk][3], bf);
            }
        }
        __syncthreads();

        int rem = T - kb;
        if (rem < 64) {
            #pragma unroll
            for (int j = 0; j < 8; j++) {
                int c0 = j * 8 + t * 2, c1 = c0 + 1;
                if (c0 >= rem) { sc[j][0] = -1e30f; sc[j][2] = -1e30f; }
                if (c1 >= rem) { sc[j][1] = -1e30f; sc[j][3] = -1e30f; }
            }
        }
        float mx0 = -1e30f, mx1 = -1e30f;
        #pragma unroll
        for (int j = 0; j < 8; j++) {
            mx0 = fmaxf(mx0, fmaxf(sc[j][0], sc[j][1]));
            mx1 = fmaxf(mx1, fmaxf(sc[j][2], sc[j][3]));
        }
        mx0 = fmaxf(mx0, __shfl_xor_sync(0xffffffffu, mx0, 1));
        mx0 = fmaxf(mx0, __shfl_xor_sync(0xffffffffu, mx0, 2));
        mx1 = fmaxf(mx1, __shfl_xor_sync(0xffffffffu, mx1, 1));
        mx1 = fmaxf(mx1, __shfl_xor_sync(0xffffffffu, mx1, 2));
        float mn0 = fmaxf(m0, mx0), mn1 = fmaxf(m1, mx1);
        float corr0 = __expf(m0 - mn0), corr1 = __expf(m1 - mn1);
        m0 = mn0; m1 = mn1;
        float sum0 = 0.f, sum1 = 0.f;
        #pragma unroll
        for (int j = 0; j < 8; j++) {
            sc[j][0] = __expf(sc[j][0] - mn0); sum0 += sc[j][0];
            sc[j][1] = __expf(sc[j][1] - mn0); sum0 += sc[j][1];
            sc[j][2] = __expf(sc[j][2] - mn1); sum1 += sc[j][2];
            sc[j][3] = __expf(sc[j][3] - mn1); sum1 += sc[j][3];
        }
        sum0 += __shfl_xor_sync(0xffffffffu, sum0, 1);
        sum0 += __shfl_xor_sync(0xffffffffu, sum0, 2);
        sum1 += __shfl_xor_sync(0xffffffffu, sum1, 1);
        sum1 += __shfl_xor_sync(0xffffffffu, sum1, 2);
        l0 = l0 * corr0 + sum0;
        l1 = l1 * corr1 + sum1;
        #pragma unroll
        for (int j = 0; j < 8; j++) {
            oc[j][0] *= corr0; oc[j][1] *= corr0;
            oc[j][2] *= corr1; oc[j][3] *= corr1;
        }

        {
            float* pb = kp + w * 1024;
            #pragma unroll
            for (int j = 0; j < 8; j++) {
                #pragma unroll
                for (int e = 0; e < 2; e++) {
                    int kcol = t * 2 + e;
                    int base = j * 128 + (g * 4 + (kcol & 3)) * 4 + ((kcol >= 4) ? 2 : 0);
                    pb[base + 0] = __uint_as_float(ftf32(sc[j][e]));
                    pb[base + 1] = __uint_as_float(ftf32(sc[j][2 + e]));
                }
            }
        }
        __syncwarp();

        const float* pb = kp + w * 1024;
        #pragma unroll
        for (int kk = 0; kk < 8; kk++) {
            uint4 pf = *(const uint4*)&pb[kk * 128 + lane * 4];
            #pragma unroll
            for (int j = 0; j < 8; j++) {
                uint2 bh2 = *(const uint2*)&vhi[(kk * 8 + j) * 64 + lane * 2];
                MMA_TF32(oc[j], pf, bh2);
                uint2 bl2 = *(const uint2*)&vlo[(kk * 8 + j) * 64 + lane * 2];
                MMA_TF32(oc[j], pf, bl2);
            }
        }
    }

    float inv0 = 1.f / l0, inv1 = 1.f / l1;
    int gr0 = b * T + r0, gr1 = b * T + r1;
    #pragma unroll
    for (int j = 0; j < 8; j++) {
        int c0 = head * HD + j * 8 + t * 2;
        if (r0 < T) {
            store_frag(aoF, DM, gr0, c0 + 0, oc[j][0] * inv0);
            store_frag(aoF, DM, gr0, c0 + 1, oc[j][1] * inv0);
        }
        if (r1 < T) {
            store_frag(aoF, DM, gr1, c0 + 0, oc[j][2] * inv1);
            store_frag(aoF, DM, gr1, c0 + 1, oc[j][3] * inv1);
        }
    }
}

// ---------------- encoder (writes h + hF) ----------------
__global__ void enc_kernel(const float* __restrict__ x,
                           const float* __restrict__ W_enc,
                           const float* __restrict__ b_enc,
                           const float* __restrict__ cls_tok,
                           const float* __restrict__ pos_emb,
                           float* __restrict__ h, float* __restrict__ hF)
{
    int row = blockIdx.x;
    int b = row / T, t = row % T;
    int tid = threadIdx.x;           // 128
    float* hr = h + (size_t)row * DM;
    if (t == 0) {
        for (int d = tid; d < DM; d += 128) {
            float val = cls_tok[d] + pos_emb[d];
            hr[d] = val;
            store_frag(hF, DM, row, d, val);
        }
        return;
    }
    __shared__ float xs[NTOK];
    if (tid < NTOK) xs[tid] = x[(size_t)b * SEQ * NTOK + (size_t)(t - 1) * NTOK + tid];
    __syncthreads();
    for (int d = tid; d < DM; d += 128) {
        float acc = b_enc[d] + pos_emb[(size_t)t * DM + d];
        #pragma unroll 17
        for (int kk = 0; kk < NTOK; kk++)
            acc += xs[kk] * W_enc[kk * DM + d];
        hr[d] = acc;
        store_frag(hF, DM, row, d, acc);
    }
}

// ---------------- residual add + layernorm (float4, writes h + hF) ----------------
__global__ void add_ln_kernel(float* __restrict__ h, const float* __restrict__ f,
                              const float* __restrict__ gamma, const float* __restrict__ beta,
                              float* __restrict__ hF)
{
    int row = blockIdx.x;
    int tid = threadIdx.x;  // 128, each owns cols [tid*4, tid*4+4)
    float* hr = h + (size_t)row * DM;
    const float* fr = f + (size_t)row * DM;
    float4 hv = ((const float4*)hr)[tid];
    float4 fv = ((const float4*)fr)[tid];
    float v[4] = { hv.x + fv.x, hv.y + fv.y, hv.z + fv.z, hv.w + fv.w };
    float s = v[0] + v[1] + v[2] + v[3];
    __shared__ float sm2[4];
    int lane = tid & 31, warp = tid >> 5;
    #pragma unroll
    for (int off = 16; off >= 1; off >>= 1) s += __shfl_xor_sync(0xffffffffu, s, off);
    if (lane == 0) sm2[warp] = s;
    __syncthreads();
    float mean = (sm2[0] + sm2[1] + sm2[2] + sm2[3]) * (1.f / DM);
    float vs = 0.f;
    #pragma unroll
    for (int i = 0; i < 4; i++) { float d = v[i] - mean; vs += d * d; }
    __syncthreads();
    #pragma unroll
    for (int off = 16; off >= 1; off >>= 1) vs += __shfl_xor_sync(0xffffffffu, vs, off);
    if (lane == 0) sm2[warp] = vs;
    __syncthreads();
    float var = (sm2[0] + sm2[1] + sm2[2] + sm2[3]) * (1.f / DM);
    float inv = rsqrtf(var + 1e-5f);
    float4 gv = ((const float4*)gamma)[tid];
    float4 bv = ((const float4*)beta)[tid];
    float4 ov;
    ov.x = (v[0] - mean) * inv * gv.x + bv.x;
    ov.y = (v[1] - mean) * inv * gv.y + bv.y;
    ov.z = (v[2] - mean) * inv * gv.z + bv.z;
    ov.w = (v[3] - mean) * inv * gv.w + bv.w;
    ((float4*)hr)[tid] = ov;
    int d0 = tid * 4;
    store_frag(hF, DM, row, d0 + 0, ov.x);
    store_frag(hF, DM, row, d0 + 1, ov.y);
    store_frag(hF, DM, row, d0 + 2, ov.z);
    store_frag(hF, DM, row, d0 + 3, ov.w);
}

// ---------------- classification head ----------------
__global__ void head_kernel(const float* __restrict__ h,
                            const float* __restrict__ Wd1, const float* __restrict__ bd1,
                            const float* __restrict__ Wd2, const float* __restrict__ bd2,
                            float* __restrict__ out)
{
    __shared__ float mid[NB][MLPD];
    int tid = threadIdx.x; // 256
    for (int b = 0; b < NB; b++) {
        const float* cls = h + (size_t)b * T * DM;
        float acc = bd1[tid];
        for (int kk = 0; kk < DM; kk++)
            acc += cls[kk] * Wd1[kk * MLPD + tid];
        mid[b][tid] = acc;
    }
    __syncthreads();
    if (tid < NB * CLASSES) {
        int b = tid / CLASSES, c = tid % CLASSES;
        float acc = bd2[c];
        for (int m = 0; m < MLPD; m++)
            acc += mid[b][m] * Wd2[m * CLASSES + c];
        out[b * CLASSES + c] = acc;
    }
}

// ---------------- GAT branch ----------------
__global__ __launch_bounds__(256) void gat_kernel(
    const float* __restrict__ x, const int* __restrict__ adj,
    const float* __restrict__ Wg, const float* __restrict__ ag,
    const float* __restrict__ Wgo, const float* __restrict__ ago,
    float* __restrict__ out)
{
    int wid = threadIdx.x >> 5, lane = threadIdx.x & 31;
    int gidx = blockIdx.x * 8 + wid;
    int s = gidx / 5, g = gidx % 5;

    float xg[5][3];
    const float* xb = x + (size_t)s * NTOK + g * 3;
    #pragma unroll
    for (int n = 0; n < 5; n++)
        #pragma unroll
        for (int c = 0; c < 3; c++)
            xg[n][c] = xb[(size_t)n * SEQ * NTOK + c];

    int av = (lane < 25) ? adj[lane] : 0;
    unsigned mb = __ballot_sync(0xffffffffu, av > 0);

    float hcat[GH][5][2];
    #pragma unroll
    for (int hd = 0; hd < GH; hd++) {
        const float* W = Wg + hd * 3 * GHID;
        float w00 = W[lane],      w01 = W[GHID + lane],      w02 = W[2 * GHID + lane];
        float w10 = W[32 + lane], w11 = W[GHID + 32 + lane], w12 = W[2 * GHID + 32 + lane];
        float a1l = ag[hd * 2 * GHID + lane];
        float a1h = ag[hd * 2 * GHID + 32 + lane];
        float a2l = ag[hd * 2 * GHID + GHID + lane];
        float a2h = ag[hd * 2 * GHID + GHID + 32 + lane];
        float hv[5][2];
        #pragma unroll
        for (int n = 0; n < 5; n++) {
            hv[n][0] = xg[n][0] * w00 + xg[n][1] * w01 + xg[n][2] * w02;
            hv[n][1] = xg[n][0] * w10 + xg[n][1] * w11 + xg[n][2] * w12;
        }
        float s1[5], s2[5];
        #pragma unroll
        for (int n = 0; n < 5; n++) {
            float p1 = hv[n][0] * a1l + hv[n][1] * a1h;
            float p2 = hv[n][0] * a2l + hv[n][1] * a2h;
            #pragma unroll
            for (int off = 16; off >= 1; off >>= 1) {
                p1 += __shfl_xor_sync(0xffffffffu, p1, off);
                p2 += __shfl_xor_sync(0xffffffffu, p2, off);
            }
            s1[n] = p1; s2[n] = p2;
        }
        float att[5][5];
        #pragma unroll
        for (int i = 0; i < 5; i++) {
            float ev[5], mx = -1e30f;
            #pragma unroll
            for (int j = 0; j < 5; j++) {
                if ((mb >> (i * 5 + j)) & 1) {
                    float e = s1[i] + s2[j];
                    e = e > 0.f ? e : 0.2f * e;
                    ev[j] = e;
                    mx = fmaxf(mx, e);
                } else ev[j] = -1e30f;
            }
            float sum = 0.f;
            #pragma unroll
            for (int j = 0; j < 5; j++) {
                float p = ((mb >> (i * 5 + j)) & 1) ? __expf(ev[j] - mx) : 0.f;
                att[i][j] = p; sum += p;
            }
            float inv = 1.f / sum;
            #pragma unroll
            for (int j = 0; j < 5; j++) att[i][j] *= inv;
        }
        #pragma unroll
        for (int n = 0; n < 5; n++) {
            float o0 = 0.f, o1 = 0.f;
            #pragma unroll
            for (int j = 0; j < 5; j++) {
                o0 += att[n][j] * hv[j][0];
                o1 += att[n][j] * hv[j][1];
            }
            hcat[hd][n][0] = o0 > 0.f ? o0 : expm1f(o0);
            hcat[hd][n][1] = o1 > 0.f ? o1 : expm1f(o1);
        }
    }

    float wg0[GH][GCLS], wg1[GH][GCLS];
    #pragma unroll
    for (int hd = 0; hd < GH; hd++)
        #pragma unroll
        for (int m = 0; m < GCLS; m++) {
            wg0[hd][m] = Wgo[(hd * GHID + lane) * GCLS + m];
            wg1[hd][m] = Wgo[(hd * GHID + 32 + lane) * GCLS + m];
        }
    float h2[5][5];
    #pragma unroll
    for (int n = 0; n < 5; n++)
        #pragma unroll
        for (int m = 0; m < 5; m++) {
            float acc = 0.f;
            #pragma unroll
            for (int hd = 0; hd < GH; hd++)
                acc += hcat[hd][n][0] * wg0[hd][m] + hcat[hd][n][1] * wg1[hd][m];
            #pragma unroll
            for (int off = 16; off >= 1; off >>= 1)
                acc += __shfl_xor_sync(0xffffffffu, acc, off);
            h2[n][m] = acc;
        }

    float s1o[5], s2o[5];
    #pragma unroll
    for (int n = 0; n < 5; n++) {
        float a1 = 0.f, a2 = 0.f;
        #pragma unroll
        for (int m = 0; m < 5; m++) {
            a1 += h2[n][m] * ago[m];
            a2 += h2[n][m] * ago[GCLS + m];
        }
        s1o[n] = a1; s2o[n] = a2;
    }
    float att2[5][5];
    #pragma unroll
    for (int i = 0; i < 5; i++) {
        float ev[5], mx = -1e30f;
        #pragma unroll
        for (int j = 0; j < 5; j++) {
            if ((mb >> (i * 5 + j)) & 1) {
                float e = s1o[i] + s2o[j];
                e = e > 0.f ? e : 0.2f * e;
                ev[j] = e;
                mx = fmaxf(mx, e);
            } else ev[j] = -1e30f;
        }
        float sum = 0.f;
        #pragma unroll
        for (int j = 0; j < 5; j++) {
            float p = ((mb >> (i * 5 + j)) & 1) ? __expf(ev[j] - mx) : 0.f;
            att2[i][j] = p; sum += p;
        }
        float inv = 1.f / sum;
        #pragma unroll
        for (int j = 0; j < 5; j++) att2[i][j] *= inv;
    }
    float o2[5][5];
    #pragma unroll
    for (int n = 0; n < 5; n++)
        #pragma unroll
        for (int m = 0; m < 5; m++) {
            float o = 0.f;
            #pragma unroll
            for (int j = 0; j < 5; j++) o += att2[n][j] * h2[j][m];
            o2[n][m] = o > 0.f ? o : expm1f(o);
        }
    if (lane < 25) {
        int n = lane / 5;
        float mx = -1e30f;
        #pragma unroll
        for (int m = 0; m < 5; m++) mx = fmaxf(mx, o2[n][m]);
        float sum = 0.f;
        #pragma unroll
        for (int m = 0; m < 5; m++) sum += __expf(o2[n][m] - mx);
        float lse = mx + logf(sum);
        out[OUT_GAT_BASE + (size_t)gidx * 25 + lane] = o2[n][lane % 5] - lse;
    }
}

// ---------------- host orchestration ----------------
extern "C" void kernel_launch(void* const* d_in, const int* in_sizes, int n_in,
                              void* d_out, int out_size)
{
    const float* x       = (const float*)d_in[0];
    const int*   adj     = (const int*)  d_in[1];
    const float* W_enc   = (const float*)d_in[2];
    const float* b_enc   = (const float*)d_in[3];
    const float* cls_tok = (const float*)d_in[4];
    const float* pos_emb = (const float*)d_in[5];
    const float* Wq      = (const float*)d_in[6];
    const float* bq      = (const float*)d_in[7];
    const float* Wk      = (const float*)d_in[8];
    const float* bk      = (const float*)d_in[9];
    const float* Wv      = (const float*)d_in[10];
    const float* bv      = (const float*)d_in[11];
    const float* Wo      = (const float*)d_in[12];
    const float* bo      = (const float*)d_in[13];
    const float* W1      = (const float*)d_in[14];
    const float* b1      = (const float*)d_in[15];
    const float* W2      = (const float*)d_in[16];
    const float* b2      = (const float*)d_in[17];
    const float* g1      = (const float*)d_in[18];
    const float* be1     = (const float*)d_in[19];
    const float* g2      = (const float*)d_in[20];
    const float* be2     = (const float*)d_in[21];
    const float* Wd1     = (const float*)d_in[22];
    const float* bd1     = (const float*)d_in[23];
    const float* Wd2     = (const float*)d_in[24];
    const float* bd2     = (const float*)d_in[25];
    const float* Wg      = (const float*)d_in[26];
    const float* ag      = (const float*)d_in[27];
    const float* Wgo     = (const float*)d_in[28];
    const float* ago     = (const float*)d_in[29];
    float* out = (float*)d_out;

    float *h, *q, *t;
    float *hF, *ffF, *aoF;
    float *WqF, *WkF, *WvF, *WoF, *W1F, *W2F;
    float *kF, *vhiF, *vloF;
    cudaGetSymbolAddress((void**)&h,    g_h);
    cudaGetSymbolAddress((void**)&q,    g_q);
    cudaGetSymbolAddress((void**)&t,    g_t);
    cudaGetSymbolAddress((void**)&hF,   g_hF);
    cudaGetSymbolAddress((void**)&ffF,  g_ffF);
    cudaGetSymbolAddress((void**)&aoF,  g_aoF);
    cudaGetSymbolAddress((void**)&WqF,  g_WqF);
    cudaGetSymbolAddress((void**)&WkF,  g_WkF);
    cudaGetSymbolAddress((void**)&WvF,  g_WvF);
    cudaGetSymbolAddress((void**)&WoF,  g_WoF);
    cudaGetSymbolAddress((void**)&W1F,  g_W1F);
    cudaGetSymbolAddress((void**)&W2F,  g_W2F);
    cudaGetSymbolAddress((void**)&kF,   g_kF);
    cudaGetSymbolAddress((void**)&vhiF, g_vhiF);
    cudaGetSymbolAddress((void**)&vloF, g_vloF);

    cudaFuncSetAttribute(attn_mma_kernel, cudaFuncAttributeMaxDynamicSharedMemorySize, ATT_SMEM);

    frag_all<<<12288, 256>>>(Wq, Wk, Wv, Wo, W1, W2, WqF, WkF, WvF, WoF, W1F, W2F);

    gat_kernel<<<GAT_GRAPHS / 8, 256>>>(x, adj, Wg, ag, Wgo, ago, out);
    enc_kernel<<<MROWS, 128>>>(x, W_enc, b_enc, cls_tok, pos_emb, h, hF);

    dim3 grid_qkv(DM / 64, NBLK, 3);
    dim3 grid_dm(DM / 64, NBLK);
    dim3 grid_ff(DFF / 64, NBLK);
    dim3 attn_grid((T + 127) / 128, NHEAD, NB);

    for (int l = 0; l < NL; l++) {
        mma_gemm_qkv_fA<<<grid_qkv, 256>>>(
            hF, WqF + (size_t)l * DM * DM, WkF + (size_t)l * DM * DM, WvF + (size_t)l * DM * DM,
            bq + l * DM, bk + l * DM, bv + l * DM, q, kF, vhiF, vloF);
        attn_mma_kernel<<<attn_grid, 256, ATT_SMEM>>>(q, kF, vhiF, vloF, aoF);
        mma_gemm_fA<<<grid_dm, 256>>>(aoF, WoF + (size_t)l * DM * DM, bo + l * DM,
                                      t, nullptr, MROWS, DM, DM, 0);
        add_ln_kernel<<<MROWS, 128>>>(h, t, g1 + l * DM, be1 + l * DM, hF);
        mma_gemm_fA<<<grid_ff, 256>>>(hF, W1F + (size_t)l * DM * DFF, b1 + l * DFF,
                                      nullptr, ffF, MROWS, DFF, DM, 1);
        mma_gemm_fA<<<grid_dm, 256>>>(ffF, W2F + (size_t)l * DFF * DM, b2 + l * DM,
                                      t, nullptr, MROWS, DM, DFF, 0);
        add_ln_kernel<<<MROWS, 128>>>(h, t, g2 + l * DM, be2 + l * DM, hF);
    }

    head_kernel<<<1, 256>>>(h, Wd1, bd1, Wd2, bd2, out);
}

// round 15
// speedup vs baseline: 1.0093x; 1.0093x over previous
#include <cuda_runtime.h>
#include <cuda_bf16.h>
#include <math.h>
#include <stdint.h>

// ---------------- problem constants ----------------
#define NB 5
#define SEQ 1024
#define T 1025
#define DM 512
#define NHEAD 8
#define HD 64
#define DFF 2048
#define NL 4
#define NTOK 51
#define MLPD 256
#define CLASSES 7
#define GH 3
#define GHID 64
#define GCLS 5
#define MROWS (NB * T)
#define NBLK 41
#define GAT_GRAPHS (SEQ * 5)
#define OUT_GAT_BASE (NB * CLASSES)
#define NWIN 17
#define KV_PER_HEAD (NWIN * 4096)

// ---------------- scratch ----------------
__device__ float g_h [MROWS * DM];
__device__ float g_q [MROWS * DM];
__device__ float g_t [MROWS * DM];
// fragment-packed activations (zero-init tails)
__device__ float g_hF [NBLK * 128 * DM];
__device__ float g_ffF[NBLK * 128 * DFF];
__device__ float g_aoF[NBLK * 128 * DM];
// fragment-packed (tf32-rounded) weights
__device__ float g_WqF[NL * DM * DM];
__device__ float g_WkF[NL * DM * DM];
__device__ float g_WvF[NL * DM * DM];
__device__ float g_WoF[NL * DM * DM];
__device__ float g_W1F[NL * DM * DFF];
__device__ float g_W2F[NL * DFF * DM];
// fragment-packed K / V(hi,lo)  (invalid keys stay zero from static init)
__device__ float g_kF  [NB * NHEAD * KV_PER_HEAD];
__device__ float g_vhiF[NB * NHEAD * KV_PER_HEAD];
__device__ float g_vloF[NB * NHEAD * KV_PER_HEAD];

// ---------------- helpers ----------------
__device__ __forceinline__ uint32_t ftf32(float x) {
    uint32_t r;
    asm("cvt.rna.tf32.f32 %0, %1;" : "=r"(r) : "f"(x));
    return r;
}

#define MMA_TF32(d, a, b) \
    asm volatile("mma.sync.aligned.m16n8k8.row.col.f32.tf32.tf32.f32 " \
        "{%0,%1,%2,%3}, {%4,%5,%6,%7}, {%8,%9}, {%0,%1,%2,%3};" \
        : "+f"((d)[0]), "+f"((d)[1]), "+f"((d)[2]), "+f"((d)[3]) \
        : "r"((a).x), "r"((a).y), "r"((a).z), "r"((a).w), \
          "r"((b).x), "r"((b).y))

#define MMA_TF32_P(d, a0, a1, a2, a3, b) \
    asm volatile("mma.sync.aligned.m16n8k8.row.col.f32.tf32.tf32.f32 " \
        "{%0,%1,%2,%3}, {%4,%5,%6,%7}, {%8,%9}, {%0,%1,%2,%3};" \
        : "+f"((d)[0]), "+f"((d)[1]), "+f"((d)[2]), "+f"((d)[3]) \
        : "r"(a0), "r"(a1), "r"(a2), "r"(a3), \
          "r"((b).x), "r"((b).y))

// store value into A-fragment layout (per 128-row block, width Ncols)
__device__ __forceinline__ void store_frag(float* F, int Ncols, int row, int col, float val) {
    size_t slot = (size_t)(row >> 7) * 128 * Ncols
        + (size_t)((col >> 3) * 8 + ((row & 127) >> 4)) * 128
        + ((row & 7) * 4 + (col & 3)) * 4
        + (((col & 7) >= 4) ? 2 : 0) + ((row >> 3) & 1);
    F[slot] = __uint_as_float(ftf32(val));
}

// ---------------- weight -> B-fragment packing ----------------
__global__ __launch_bounds__(256) void frag_all(
    const float* __restrict__ Wq, const float* __restrict__ Wk,
    const float* __restrict__ Wv, const float* __restrict__ Wo,
    const float* __restrict__ W1, const float* __restrict__ W2,
    float* __restrict__ WqF, float* __restrict__ WkF,
    float* __restrict__ WvF, float* __restrict__ WoF,
    float* __restrict__ W1F, float* __restrict__ W2F)
{
    __shared__ float t[32][33];
    int bid = blockIdx.x;
    const float* W; float* Wf; int K, N, rel, nx;
    if (bid < 4096) {
        int job = bid >> 10; rel = bid & 1023;
        K = DM; N = DM; nx = 16;
        if (job == 0)      { W = Wq; Wf = WqF; }
        else if (job == 1) { W = Wk; Wf = WkF; }
        else if (job == 2) { W = Wv; Wf = WvF; }
        else               { W = Wo; Wf = WoF; }
    } else if (bid < 8192) {
        rel = bid - 4096; K = DM; N = DFF; nx = 64;
        W = W1; Wf = W1F;
    } else {
        rel = bid - 8192; K = DFF; N = DM; nx = 16;
        W = W2; Wf = W2F;
    }
    int ny = K >> 5;
    int per = nx * ny;
    int l = rel / per, r2 = rel % per;
    int n0 = (r2 % nx) * 32, k0 = (r2 / nx) * 32;
    const float* w = W + (size_t)l * K * N;
    float* o = Wf + (size_t)l * K * N;
    int tx = threadIdx.x & 31, ty = threadIdx.x >> 5;
    #pragma unroll
    for (int i = 0; i < 32; i += 8)
        t[ty + i][tx] = w[(size_t)(k0 + ty + i) * N + n0 + tx];
    __syncthreads();
    int Kt = K >> 3;
    #pragma unroll
    for (int it = 0; it < 4; it++) {
        int w2 = threadIdx.x + it * 256;
        int group = w2 >> 6, within = w2 & 63;
        int ktl = group & 3, ntl = group >> 2;
        int lane = within >> 1, r = within & 1;
        int kk = ktl * 8 + (lane & 3) + r * 4;
        int nn = ntl * 8 + (lane >> 2);
        o[((size_t)((n0 >> 3) + ntl) * Kt + (k0 >> 3) + ktl) * 64 + within]
            = __uint_as_float(ftf32(t[kk][nn]));
    }
}

// ---------------- frag-A GEMM: 128x64 CTA tile, 64x16 warp tile ----------------
__device__ __forceinline__ void mma_gemm_fA_body(
    const float* __restrict__ Af, const float* __restrict__ Bf,
    const float* __restrict__ bias, float* __restrict__ C,
    float* __restrict__ Cf, int M, int N, int K, int relu)
{
    int tid = threadIdx.x;
    int w = tid >> 5, lane = tid & 31;
    int bm = blockIdx.y * 128, bn = blockIdx.x * 64;
    int wm = (w & 1) * 64, wn = (w >> 1) * 16;
    int Kt = K >> 3;
    int nt0 = (bn + wn) >> 3;
    int mtw = wm >> 4;
    const float* Ab = Af + (size_t)blockIdx.y * 128 * K;

    float d[4][2][4];
    #pragma unroll
    for (int i = 0; i < 4; i++)
        #pragma unroll
        for (int j = 0; j < 2; j++)
            #pragma unroll
            for (int e = 0; e < 4; e++) d[i][j][e] = 0.f;

    uint4 ac[4];
    uint2 bc[2], bnx[2];
    #pragma unroll
    for (int i = 0; i < 4; i++)
        ac[i] = *(const uint4*)(Ab + ((mtw + i) * 32 + lane) * 4);
    #pragma unroll
    for (int j = 0; j < 2; j++)
        bc[j] = *(const uint2*)(Bf + ((size_t)(nt0 + j) * Kt) * 64 + lane * 2);

    for (int ktg = 0; ktg < Kt; ktg++) {
        if (ktg + 1 < Kt) {
            #pragma unroll
            for (int j = 0; j < 2; j++)
                bnx[j] = *(const uint2*)(Bf + ((size_t)(nt0 + j) * Kt + ktg + 1) * 64 + lane * 2);
        }
        #pragma unroll
        for (int i = 0; i < 4; i++)
            #pragma unroll
            for (int j = 0; j < 2; j++)
                MMA_TF32(d[i][j], ac[i], bc[j]);
        if (ktg + 1 < Kt) {
            #pragma unroll
            for (int i = 0; i < 4; i++)
                ac[i] = *(const uint4*)(Ab + (((ktg + 1) * 8 + mtw + i) * 32 + lane) * 4);
            #pragma unroll
            for (int j = 0; j < 2; j++) bc[j] = bnx[j];
        }
    }

    int g = lane >> 2, t2 = (lane & 3) << 1;
    if (Cf) {
        size_t cb = (size_t)blockIdx.y * 128 * N;
        #pragma unroll
        for (int i = 0; i < 4; i++)
            #pragma unroll
            for (int hh = 0; hh < 2; hh++) {
                int rloc = wm + i * 16 + g + hh * 8;
                #pragma unroll
                for (int j = 0; j < 2; j++)
                    #pragma unroll
                    for (int e = 0; e < 2; e++) {
                        int col = bn + wn + j * 8 + t2 + e;
                        float val = d[i][j][hh * 2 + e] + bias[col];
                        if (relu) val = fmaxf(val, 0.f);
                        size_t slot = cb + (size_t)((col >> 3) * 8 + (rloc >> 4)) * 128
                                      + ((rloc & 7) * 4 + (col & 3)) * 4
                                      + (((col & 7) >= 4) ? 2 : 0) + hh;
                        Cf[slot] = __uint_as_float(ftf32(val));
                    }
            }
    } else {
        #pragma unroll
        for (int i = 0; i < 4; i++) {
            #pragma unroll
            for (int hh = 0; hh < 2; hh++) {
                int row = bm + wm + i * 16 + g + hh * 8;
                if (row >= M) continue;
                #pragma unroll
                for (int j = 0; j < 2; j++) {
                    int col = bn + wn + j * 8 + t2;
                    float2 bb = *(const float2*)(bias + col);
                    float2 r;
                    r.x = d[i][j][hh * 2 + 0] + bb.x;
                    r.y = d[i][j][hh * 2 + 1] + bb.y;
                    if (relu) { r.x = fmaxf(r.x, 0.f); r.y = fmaxf(r.y, 0.f); }
                    *(float2*)(C + (size_t)row * N + col) = r;
                }
            }
        }
    }
}

__global__ __launch_bounds__(256) void mma_gemm_fA(
    const float* __restrict__ Af, const float* __restrict__ Bf,
    const float* __restrict__ bias, float* __restrict__ C,
    float* __restrict__ Cf, int M, int N, int K, int relu)
{
    mma_gemm_fA_body(Af, Bf, bias, C, Cf, M, N, K, relu);
}

// ---------------- qkv GEMM: Q -> row-major, K/V -> KV fragment layouts ----------------
__global__ __launch_bounds__(256) void mma_gemm_qkv_fA(
    const float* __restrict__ Af,
    const float* __restrict__ WqF, const float* __restrict__ WkF, const float* __restrict__ WvF,
    const float* __restrict__ bq, const float* __restrict__ bk, const float* __restrict__ bv,
    float* __restrict__ q,
    float* __restrict__ kF, float* __restrict__ vhiF, float* __restrict__ vloF)
{
    const float* Bf; const float* bias;
    if (blockIdx.z == 0)      { Bf = WqF; bias = bq; }
    else if (blockIdx.z == 1) { Bf = WkF; bias = bk; }
    else                      { Bf = WvF; bias = bv; }

    int tid = threadIdx.x;
    int w = tid >> 5, lane = tid & 31;
    int bm = blockIdx.y * 128, bn = blockIdx.x * 64;
    int wm = (w & 1) * 64, wn = (w >> 1) * 16;
    int Kt = DM >> 3;
    int nt0 = (bn + wn) >> 3;
    int mtw = wm >> 4;
    const float* Ab = Af + (size_t)blockIdx.y * 128 * DM;

    float d[4][2][4];
    #pragma unroll
    for (int i = 0; i < 4; i++)
        #pragma unroll
        for (int j = 0; j < 2; j++)
            #pragma unroll
            for (int e = 0; e < 4; e++) d[i][j][e] = 0.f;

    uint4 ac[4];
    uint2 bc[2], bnx[2];
    #pragma unroll
    for (int i = 0; i < 4; i++)
        ac[i] = *(const uint4*)(Ab + ((mtw + i) * 32 + lane) * 4);
    #pragma unroll
    for (int j = 0; j < 2; j++)
        bc[j] = *(const uint2*)(Bf + ((size_t)(nt0 + j) * Kt) * 64 + lane * 2);

    for (int ktg = 0; ktg < Kt; ktg++) {
        if (ktg + 1 < Kt) {
            #pragma unroll
            for (int j = 0; j < 2; j++)
                bnx[j] = *(const uint2*)(Bf + ((size_t)(nt0 + j) * Kt + ktg + 1) * 64 + lane * 2);
        }
        #pragma unroll
        for (int i = 0; i < 4; i++)
            #pragma unroll
            for (int j = 0; j < 2; j++)
                MMA_TF32(d[i][j], ac[i], bc[j]);
        if (ktg + 1 < Kt) {
            #pragma unroll
            for (int i = 0; i < 4; i++)
                ac[i] = *(const uint4*)(Ab + (((ktg + 1) * 8 + mtw + i) * 32 + lane) * 4);
            #pragma unroll
            for (int j = 0; j < 2; j++) bc[j] = bnx[j];
        }
    }

    int g = lane >> 2, t2 = (lane & 3) << 1;
    if (blockIdx.z == 0) {
        #pragma unroll
        for (int i = 0; i < 4; i++) {
            #pragma unroll
            for (int hh = 0; hh < 2; hh++) {
                int row = bm + wm + i * 16 + g + hh * 8;
                if (row >= MROWS) continue;
                #pragma unroll
                for (int j = 0; j < 2; j++) {
                    int col = bn + wn + j * 8 + t2;
                    float2 bb = *(const float2*)(bias + col);
                    float2 r;
                    r.x = d[i][j][hh * 2 + 0] + bb.x;
                    r.y = d[i][j][hh * 2 + 1] + bb.y;
                    *(float2*)(q + (size_t)row * DM + col) = r;
                }
            }
        }
    } else {
        int isK = (blockIdx.z == 1);
        #pragma unroll
        for (int i = 0; i < 4; i++) {
            #pragma unroll
            for (int hh = 0; hh < 2; hh++) {
                int row = bm + wm + i * 16 + g + hh * 8;
                if (row >= MROWS) continue;
                int b = row / T, t = row % T;
                int win = t >> 6, key = t & 63;
                #pragma unroll
                for (int j = 0; j < 2; j++) {
                    #pragma unroll
                    for (int e = 0; e < 2; e++) {
                        int col = bn + wn + j * 8 + t2 + e;
                        float val = d[i][j][hh * 2 + e] + bias[col];
                        int head = col >> 6, dd = col & 63;
                        size_t base = (((size_t)(b * NHEAD + head) * NWIN + win)) * 4096;
                        if (isK) {
                            kF[base + ((dd >> 3) * 8 + (key >> 3)) * 64
                               + ((key & 7) * 4 + (dd & 3)) * 2 + ((dd & 7) >> 2)]
                                = __uint_as_float(ftf32(val));
                        } else {
                            uint32_t hb = ftf32(val);
                            float hf = __uint_as_float(hb);
                            uint32_t lb = ftf32(val - hf);
                            size_t a2 = base + ((key >> 3) * 8 + (dd >> 3)) * 64
                                        + ((dd & 7) * 4 + (key & 3)) * 2 + ((key & 7) >> 2);
                            vhiF[a2] = __uint_as_float(hb);
                            vloF[a2] = __uint_as_float(lb);
                        }
                    }
                }
            }
        }
    }
}

// ---------------- tf32 mma.sync flash attention -> frag output ----------------
#define ATT_SMEM 65536

__global__ __launch_bounds__(256) void attn_mma_kernel(
    const float* __restrict__ q,
    const float* __restrict__ kF, const float* __restrict__ vhiF,
    const float* __restrict__ vloF, float* __restrict__ aoF)
{
    extern __shared__ float as_[];
    float* kp  = as_;
    float* vhi = as_ + 8192;
    float* vlo = as_ + 12288;

    int tid = threadIdx.x;
    int w = tid >> 5, lane = tid & 31;
    int g = lane >> 2, t = lane & 3;
    int qb = blockIdx.x * 128;
    int head = blockIdx.y, b = blockIdx.z;
    int bh = b * NHEAD + head;
    const float* qp = q + (size_t)b * T * DM + head * HD;
    const float* kFb = kF   + (size_t)bh * KV_PER_HEAD;
    const float* vhb = vhiF + (size_t)bh * KV_PER_HEAD;
    const float* vlb = vloF + (size_t)bh * KV_PER_HEAD;

    int r0 = qb + w * 16 + g;
    int r1 = r0 + 8;
    uint32_t aq[8][4];
    #pragma unroll
    for (int kk = 0; kk < 8; kk++) {
        int d0 = kk * 8 + t, d1 = d0 + 4;
        float q00 = 0.f, q01 = 0.f, q10 = 0.f, q11 = 0.f;
        if (r0 < T) { q00 = qp[(size_t)r0 * DM + d0]; q01 = qp[(size_t)r0 * DM + d1]; }
        if (r1 < T) { q10 = qp[(size_t)r1 * DM + d0]; q11 = qp[(size_t)r1 * DM + d1]; }
        aq[kk][0] = ftf32(q00 * 0.125f);
        aq[kk][1] = ftf32(q10 * 0.125f);
        aq[kk][2] = ftf32(q01 * 0.125f);
        aq[kk][3] = ftf32(q11 * 0.125f);
    }

    float oc[8][4];
    #pragma unroll
    for (int j = 0; j < 8; j++)
        #pragma unroll
        for (int e = 0; e < 4; e++) oc[j][e] = 0.f;
    float m0 = -1e30f, m1 = -1e30f, l0 = 0.f, l1 = 0.f;

    for (int win = 0; win < NWIN; win++) {
        int kb = win * 64;
        __syncthreads();
        {
            const float4* ks = (const float4*)(kFb + (size_t)win * 4096);
            const float4* hs = (const float4*)(vhb + (size_t)win * 4096);
            const float4* ls = (const float4*)(vlb + (size_t)win * 4096);
            float4* kd = (float4*)kp;
            float4* hd = (float4*)vhi;
            float4* ld = (float4*)vlo;
            #pragma unroll
            for (int i = 0; i < 4; i++) {
                int idx = tid + i * 256;
                kd[idx] = ks[idx];
                hd[idx] = hs[idx];
                ld[idx] = ls[idx];
            }
        }
        __syncthreads();

        float sc[8][4];
        #pragma unroll
        for (int j = 0; j < 8; j++)
            #pragma unroll
            for (int e = 0; e < 4; e++) sc[j][e] = 0.f;
        #pragma unroll
        for (int kk = 0; kk < 8; kk++) {
            #pragma unroll
            for (int j = 0; j < 8; j++) {
                uint2 bf = *(const uint2*)&kp[(kk * 8 + j) * 64 + lane * 2];
                MMA_TF32_P(sc[j], aq[kk][0], aq[kk][1], aq[kk][2], aq[kk][3], bf);
            }
        }
        __syncthreads();

        int rem = T - kb;
        if (rem < 64) {
            #pragma unroll
            for (int j = 0; j < 8; j++) {
                int c0 = j * 8 + t * 2, c1 = c0 + 1;
                if (c0 >= rem) { sc[j][0] = -1e30f; sc[j][2] = -1e30f; }
                if (c1 >= rem) { sc[j][1] = -1e30f; sc[j][3] = -1e30f; }
            }
        }
        float mx0 = -1e30f, mx1 = -1e30f;
        #pragma unroll
        for (int j = 0; j < 8; j++) {
            mx0 = fmaxf(mx0, fmaxf(sc[j][0], sc[j][1]));
            mx1 = fmaxf(mx1, fmaxf(sc[j][2], sc[j][3]));
        }
        mx0 = fmaxf(mx0, __shfl_xor_sync(0xffffffffu, mx0, 1));
        mx0 = fmaxf(mx0, __shfl_xor_sync(0xffffffffu, mx0, 2));
        mx1 = fmaxf(mx1, __shfl_xor_sync(0xffffffffu, mx1, 1));
        mx1 = fmaxf(mx1, __shfl_xor_sync(0xffffffffu, mx1, 2));
        float mn0 = fmaxf(m0, mx0), mn1 = fmaxf(m1, mx1);
        float corr0 = __expf(m0 - mn0), corr1 = __expf(m1 - mn1);
        m0 = mn0; m1 = mn1;
        float sum0 = 0.f, sum1 = 0.f;
        #pragma unroll
        for (int j = 0; j < 8; j++) {
            sc[j][0] = __expf(sc[j][0] - mn0); sum0 += sc[j][0];
            sc[j][1] = __expf(sc[j][1] - mn0); sum0 += sc[j][1];
            sc[j][2] = __expf(sc[j][2] - mn1); sum1 += sc[j][2];
            sc[j][3] = __expf(sc[j][3] - mn1); sum1 += sc[j][3];
        }
        sum0 += __shfl_xor_sync(0xffffffffu, sum0, 1);
        sum0 += __shfl_xor_sync(0xffffffffu, sum0, 2);
        sum1 += __shfl_xor_sync(0xffffffffu, sum1, 1);
        sum1 += __shfl_xor_sync(0xffffffffu, sum1, 2);
        l0 = l0 * corr0 + sum0;
        l1 = l1 * corr1 + sum1;
        #pragma unroll
        for (int j = 0; j < 8; j++) {
            oc[j][0] *= corr0; oc[j][1] *= corr0;
            oc[j][2] *= corr1; oc[j][3] *= corr1;
        }

        {
            float* pb = kp + w * 1024;
            #pragma unroll
            for (int j = 0; j < 8; j++) {
                #pragma unroll
                for (int e = 0; e < 2; e++) {
                    int kcol = t * 2 + e;
                    int base = j * 128 + (g * 4 + (kcol & 3)) * 4 + ((kcol >= 4) ? 2 : 0);
                    pb[base + 0] = __uint_as_float(ftf32(sc[j][e]));
                    pb[base + 1] = __uint_as_float(ftf32(sc[j][2 + e]));
                }
            }
        }
        __syncwarp();

        const float* pb = kp + w * 1024;
        #pragma unroll
        for (int kk = 0; kk < 8; kk++) {
            uint4 pf = *(const uint4*)&pb[kk * 128 + lane * 4];
            #pragma unroll
            for (int j = 0; j < 8; j++) {
                uint2 bh2 = *(const uint2*)&vhi[(kk * 8 + j) * 64 + lane * 2];
                MMA_TF32(oc[j], pf, bh2);
                uint2 bl2 = *(const uint2*)&vlo[(kk * 8 + j) * 64 + lane * 2];
                MMA_TF32(oc[j], pf, bl2);
            }
        }
    }

    float inv0 = 1.f / l0, inv1 = 1.f / l1;
    int gr0 = b * T + r0, gr1 = b * T + r1;
    #pragma unroll
    for (int j = 0; j < 8; j++) {
        int c0 = head * HD + j * 8 + t * 2;
        if (r0 < T) {
            store_frag(aoF, DM, gr0, c0 + 0, oc[j][0] * inv0);
            store_frag(aoF, DM, gr0, c0 + 1, oc[j][1] * inv0);
        }
        if (r1 < T) {
            store_frag(aoF, DM, gr1, c0 + 0, oc[j][2] * inv1);
            store_frag(aoF, DM, gr1, c0 + 1, oc[j][3] * inv1);
        }
    }
}

// ---------------- encoder (writes h + hF) ----------------
__global__ void enc_kernel(const float* __restrict__ x,
                           const float* __restrict__ W_enc,
                           const float* __restrict__ b_enc,
                           const float* __restrict__ cls_tok,
                           const float* __restrict__ pos_emb,
                           float* __restrict__ h, float* __restrict__ hF)
{
    int row = blockIdx.x;
    int b = row / T, t = row % T;
    int tid = threadIdx.x;           // 128
    float* hr = h + (size_t)row * DM;
    if (t == 0) {
        for (int d = tid; d < DM; d += 128) {
            float val = cls_tok[d] + pos_emb[d];
            hr[d] = val;
            store_frag(hF, DM, row, d, val);
        }
        return;
    }
    __shared__ float xs[NTOK];
    if (tid < NTOK) xs[tid] = x[(size_t)b * SEQ * NTOK + (size_t)(t - 1) * NTOK + tid];
    __syncthreads();
    for (int d = tid; d < DM; d += 128) {
        float acc = b_enc[d] + pos_emb[(size_t)t * DM + d];
        #pragma unroll 17
        for (int kk = 0; kk < NTOK; kk++)
            acc += xs[kk] * W_enc[kk * DM + d];
        hr[d] = acc;
        store_frag(hF, DM, row, d, acc);
    }
}

// ---------------- residual add + layernorm (float4, writes h + hF) ----------------
__global__ void add_ln_kernel(float* __restrict__ h, const float* __restrict__ f,
                              const float* __restrict__ gamma, const float* __restrict__ beta,
                              float* __restrict__ hF)
{
    int row = blockIdx.x;
    int tid = threadIdx.x;  // 128, each owns cols [tid*4, tid*4+4)
    float* hr = h + (size_t)row * DM;
    const float* fr = f + (size_t)row * DM;
    float4 hv = ((const float4*)hr)[tid];
    float4 fv = ((const float4*)fr)[tid];
    float v[4] = { hv.x + fv.x, hv.y + fv.y, hv.z + fv.z, hv.w + fv.w };
    float s = v[0] + v[1] + v[2] + v[3];
    __shared__ float sm2[4];
    int lane = tid & 31, warp = tid >> 5;
    #pragma unroll
    for (int off = 16; off >= 1; off >>= 1) s += __shfl_xor_sync(0xffffffffu, s, off);
    if (lane == 0) sm2[warp] = s;
    __syncthreads();
    float mean = (sm2[0] + sm2[1] + sm2[2] + sm2[3]) * (1.f / DM);
    float vs = 0.f;
    #pragma unroll
    for (int i = 0; i < 4; i++) { float d = v[i] - mean; vs += d * d; }
    __syncthreads();
    #pragma unroll
    for (int off = 16; off >= 1; off >>= 1) vs += __shfl_xor_sync(0xffffffffu, vs, off);
    if (lane == 0) sm2[warp] = vs;
    __syncthreads();
    float var = (sm2[0] + sm2[1] + sm2[2] + sm2[3]) * (1.f / DM);
    float inv = rsqrtf(var + 1e-5f);
    float4 gv = ((const float4*)gamma)[tid];
    float4 bv = ((const float4*)beta)[tid];
    float4 ov;
    ov.x = (v[0] - mean) * inv * gv.x + bv.x;
    ov.y = (v[1] - mean) * inv * gv.y + bv.y;
    ov.z = (v[2] - mean) * inv * gv.z + bv.z;
    ov.w = (v[3] - mean) * inv * gv.w + bv.w;
    ((float4*)hr)[tid] = ov;
    int d0 = tid * 4;
    store_frag(hF, DM, row, d0 + 0, ov.x);
    store_frag(hF, DM, row, d0 + 1, ov.y);
    store_frag(hF, DM, row, d0 + 2, ov.z);
    store_frag(hF, DM, row, d0 + 3, ov.w);
}

// ---------------- classification head ----------------
__global__ void head_kernel(const float* __restrict__ h,
                            const float* __restrict__ Wd1, const float* __restrict__ bd1,
                            const float* __restrict__ Wd2, const float* __restrict__ bd2,
                            float* __restrict__ out)
{
    __shared__ float mid[NB][MLPD];
    int tid = threadIdx.x; // 256
    for (int b = 0; b < NB; b++) {
        const float* cls = h + (size_t)b * T * DM;
        float acc = bd1[tid];
        for (int kk = 0; kk < DM; kk++)
            acc += cls[kk] * Wd1[kk * MLPD + tid];
        mid[b][tid] = acc;
    }
    __syncthreads();
    if (tid < NB * CLASSES) {
        int b = tid / CLASSES, c = tid % CLASSES;
        float acc = bd2[c];
        for (int m = 0; m < MLPD; m++)
            acc += mid[b][m] * Wd2[m * CLASSES + c];
        out[b * CLASSES + c] = acc;
    }
}

// ---------------- GAT branch ----------------
__global__ __launch_bounds__(256) void gat_kernel(
    const float* __restrict__ x, const int* __restrict__ adj,
    const float* __restrict__ Wg, const float* __restrict__ ag,
    const float* __restrict__ Wgo, const float* __restrict__ ago,
    float* __restrict__ out)
{
    int wid = threadIdx.x >> 5, lane = threadIdx.x & 31;
    int gidx = blockIdx.x * 8 + wid;
    int s = gidx / 5, g = gidx % 5;

    float xg[5][3];
    const float* xb = x + (size_t)s * NTOK + g * 3;
    #pragma unroll
    for (int n = 0; n < 5; n++)
        #pragma unroll
        for (int c = 0; c < 3; c++)
            xg[n][c] = xb[(size_t)n * SEQ * NTOK + c];

    int av = (lane < 25) ? adj[lane] : 0;
    unsigned mb = __ballot_sync(0xffffffffu, av > 0);

    float hcat[GH][5][2];
    #pragma unroll
    for (int hd = 0; hd < GH; hd++) {
        const float* W = Wg + hd * 3 * GHID;
        float w00 = W[lane],      w01 = W[GHID + lane],      w02 = W[2 * GHID + lane];
        float w10 = W[32 + lane], w11 = W[GHID + 32 + lane], w12 = W[2 * GHID + 32 + lane];
        float a1l = ag[hd * 2 * GHID + lane];
        float a1h = ag[hd * 2 * GHID + 32 + lane];
        float a2l = ag[hd * 2 * GHID + GHID + lane];
        float a2h = ag[hd * 2 * GHID + GHID + 32 + lane];
        float hv[5][2];
        #pragma unroll
        for (int n = 0; n < 5; n++) {
            hv[n][0] = xg[n][0] * w00 + xg[n][1] * w01 + xg[n][2] * w02;
            hv[n][1] = xg[n][0] * w10 + xg[n][1] * w11 + xg[n][2] * w12;
        }
        float s1[5], s2[5];
        #pragma unroll
        for (int n = 0; n < 5; n++) {
            float p1 = hv[n][0] * a1l + hv[n][1] * a1h;
            float p2 = hv[n][0] * a2l + hv[n][1] * a2h;
            #pragma unroll
            for (int off = 16; off >= 1; off >>= 1) {
                p1 += __shfl_xor_sync(0xffffffffu, p1, off);
                p2 += __shfl_xor_sync(0xffffffffu, p2, off);
            }
            s1[n] = p1; s2[n] = p2;
        }
        float att[5][5];
        #pragma unroll
        for (int i = 0; i < 5; i++) {
            float ev[5], mx = -1e30f;
            #pragma unroll
            for (int j = 0; j < 5; j++) {
                if ((mb >> (i * 5 + j)) & 1) {
                    float e = s1[i] + s2[j];
                    e = e > 0.f ? e : 0.2f * e;
                    ev[j] = e;
                    mx = fmaxf(mx, e);
                } else ev[j] = -1e30f;
            }
            float sum = 0.f;
            #pragma unroll
            for (int j = 0; j < 5; j++) {
                float p = ((mb >> (i * 5 + j)) & 1) ? __expf(ev[j] - mx) : 0.f;
                att[i][j] = p; sum += p;
            }
            float inv = 1.f / sum;
            #pragma unroll
            for (int j = 0; j < 5; j++) att[i][j] *= inv;
        }
        #pragma unroll
        for (int n = 0; n < 5; n++) {
            float o0 = 0.f, o1 = 0.f;
            #pragma unroll
            for (int j = 0; j < 5; j++) {
                o0 += att[n][j] * hv[j][0];
                o1 += att[n][j] * hv[j][1];
            }
            hcat[hd][n][0] = o0 > 0.f ? o0 : expm1f(o0);
            hcat[hd][n][1] = o1 > 0.f ? o1 : expm1f(o1);
        }
    }

    float wg0[GH][GCLS], wg1[GH][GCLS];
    #pragma unroll
    for (int hd = 0; hd < GH; hd++)
        #pragma unroll
        for (int m = 0; m < GCLS; m++) {
            wg0[hd][m] = Wgo[(hd * GHID + lane) * GCLS + m];
            wg1[hd][m] = Wgo[(hd * GHID + 32 + lane) * GCLS + m];
        }
    float h2[5][5];
    #pragma unroll
    for (int n = 0; n < 5; n++)
        #pragma unroll
        for (int m = 0; m < 5; m++) {
            float acc = 0.f;
            #pragma unroll
            for (int hd = 0; hd < GH; hd++)
                acc += hcat[hd][n][0] * wg0[hd][m] + hcat[hd][n][1] * wg1[hd][m];
            #pragma unroll
            for (int off = 16; off >= 1; off >>= 1)
                acc += __shfl_xor_sync(0xffffffffu, acc, off);
            h2[n][m] = acc;
        }

    float s1o[5], s2o[5];
    #pragma unroll
    for (int n = 0; n < 5; n++) {
        float a1 = 0.f, a2 = 0.f;
        #pragma unroll
        for (int m = 0; m < 5; m++) {
            a1 += h2[n][m] * ago[m];
            a2 += h2[n][m] * ago[GCLS + m];
        }
        s1o[n] = a1; s2o[n] = a2;
    }
    float att2[5][5];
    #pragma unroll
    for (int i = 0; i < 5; i++) {
        float ev[5], mx = -1e30f;
        #pragma unroll
        for (int j = 0; j < 5; j++) {
            if ((mb >> (i * 5 + j)) & 1) {
                float e = s1o[i] + s2o[j];
                e = e > 0.f ? e : 0.2f * e;
                ev[j] = e;
                mx = fmaxf(mx, e);
            } else ev[j] = -1e30f;
        }
        float sum = 0.f;
        #pragma unroll
        for (int j = 0; j < 5; j++) {
            float p = ((mb >> (i * 5 + j)) & 1) ? __expf(ev[j] - mx) : 0.f;
            att2[i][j] = p; sum += p;
        }
        float inv = 1.f / sum;
        #pragma unroll
        for (int j = 0; j < 5; j++) att2[i][j] *= inv;
    }
    float o2[5][5];
    #pragma unroll
    for (int n = 0; n < 5; n++)
        #pragma unroll
        for (int m = 0; m < 5; m++) {
            float o = 0.f;
            #pragma unroll
            for (int j = 0; j < 5; j++) o += att2[n][j] * h2[j][m];
            o2[n][m] = o > 0.f ? o : expm1f(o);
        }
    if (lane < 25) {
        int n = lane / 5;
        float mx = -1e30f;
        #pragma unroll
        for (int m = 0; m < 5; m++) mx = fmaxf(mx, o2[n][m]);
        float sum = 0.f;
        #pragma unroll
        for (int m = 0; m < 5; m++) sum += __expf(o2[n][m] - mx);
        float lse = mx + logf(sum);
        out[OUT_GAT_BASE + (size_t)gidx * 25 + lane] = o2[n][lane % 5] - lse;
    }
}

// ---------------- host orchestration ----------------
extern "C" void kernel_launch(void* const* d_in, const int* in_sizes, int n_in,
                              void* d_out, int out_size)
{
    const float* x       = (const float*)d_in[0];
    const int*   adj     = (const int*)  d_in[1];
    const float* W_enc   = (const float*)d_in[2];
    const float* b_enc   = (const float*)d_in[3];
    const float* cls_tok = (const float*)d_in[4];
    const float* pos_emb = (const float*)d_in[5];
    const float* Wq      = (const float*)d_in[6];
    const float* bq      = (const float*)d_in[7];
    const float* Wk      = (const float*)d_in[8];
    const float* bk      = (const float*)d_in[9];
    const float* Wv      = (const float*)d_in[10];
    const float* bv      = (const float*)d_in[11];
    const float* Wo      = (const float*)d_in[12];
    const float* bo      = (const float*)d_in[13];
    const float* W1      = (const float*)d_in[14];
    const float* b1      = (const float*)d_in[15];
    const float* W2      = (const float*)d_in[16];
    const float* b2      = (const float*)d_in[17];
    const float* g1      = (const float*)d_in[18];
    const float* be1     = (const float*)d_in[19];
    const float* g2      = (const float*)d_in[20];
    const float* be2     = (const float*)d_in[21];
    const float* Wd1     = (const float*)d_in[22];
    const float* bd1     = (const float*)d_in[23];
    const float* Wd2     = (const float*)d_in[24];
    const float* bd2     = (const float*)d_in[25];
    const float* Wg      = (const float*)d_in[26];
    const float* ag      = (const float*)d_in[27];
    const float* Wgo     = (const float*)d_in[28];
    const float* ago     = (const float*)d_in[29];
    float* out = (float*)d_out;

    float *h, *q, *t;
    float *hF, *ffF, *aoF;
    float *WqF, *WkF, *WvF, *WoF, *W1F, *W2F;
    float *kF, *vhiF, *vloF;
    cudaGetSymbolAddress((void**)&h,    g_h);
    cudaGetSymbolAddress((void**)&q,    g_q);
    cudaGetSymbolAddress((void**)&t,    g_t);
    cudaGetSymbolAddress((void**)&hF,   g_hF);
    cudaGetSymbolAddress((void**)&ffF,  g_ffF);
    cudaGetSymbolAddress((void**)&aoF,  g_aoF);
    cudaGetSymbolAddress((void**)&WqF,  g_WqF);
    cudaGetSymbolAddress((void**)&WkF,  g_WkF);
    cudaGetSymbolAddress((void**)&WvF,  g_WvF);
    cudaGetSymbolAddress((void**)&WoF,  g_WoF);
    cudaGetSymbolAddress((void**)&W1F,  g_W1F);
    cudaGetSymbolAddress((void**)&W2F,  g_W2F);
    cudaGetSymbolAddress((void**)&kF,   g_kF);
    cudaGetSymbolAddress((void**)&vhiF, g_vhiF);
    cudaGetSymbolAddress((void**)&vloF, g_vloF);

    cudaFuncSetAttribute(attn_mma_kernel, cudaFuncAttributeMaxDynamicSharedMemorySize, ATT_SMEM);

    frag_all<<<12288, 256>>>(Wq, Wk, Wv, Wo, W1, W2, WqF, WkF, WvF, WoF, W1F, W2F);

    gat_kernel<<<GAT_GRAPHS / 8, 256>>>(x, adj, Wg, ag, Wgo, ago, out);
    enc_kernel<<<MROWS, 128>>>(x, W_enc, b_enc, cls_tok, pos_emb, h, hF);

    dim3 grid_qkv(DM / 64, NBLK, 3);
    dim3 grid_dm(DM / 64, NBLK);
    dim3 grid_ff(DFF / 64, NBLK);
    dim3 attn_grid((T + 127) / 128, NHEAD, NB);

    for (int l = 0; l < NL; l++) {
        mma_gemm_qkv_fA<<<grid_qkv, 256>>>(
            hF, WqF + (size_t)l * DM * DM, WkF + (size_t)l * DM * DM, WvF + (size_t)l * DM * DM,
            bq + l * DM, bk + l * DM, bv + l * DM, q, kF, vhiF, vloF);
        attn_mma_kernel<<<attn_grid, 256, ATT_SMEM>>>(q, kF, vhiF, vloF, aoF);
        mma_gemm_fA<<<grid_dm, 256>>>(aoF, WoF + (size_t)l * DM * DM, bo + l * DM,
                                      t, nullptr, MROWS, DM, DM, 0);
        add_ln_kernel<<<MROWS, 128>>>(h, t, g1 + l * DM, be1 + l * DM, hF);
        mma_gemm_fA<<<grid_ff, 256>>>(hF, W1F + (size_t)l * DM * DFF, b1 + l * DFF,
                                      nullptr, ffF, MROWS, DFF, DM, 1);
        mma_gemm_fA<<<grid_dm, 256>>>(ffF, W2F + (size_t)l * DFF * DM, b2 + l * DM,
                                      t, nullptr, MROWS, DM, DFF, 0);
        add_ln_kernel<<<MROWS, 128>>>(h, t, g2 + l * DM, be2 + l * DM, hF);
    }

    head_kernel<<<1, 256>>>(h, Wd1, bd1, Wd2, bd2, out);
}

// round 16
// speedup vs baseline: 1.0208x; 1.0114x over previous
#include <cuda_runtime.h>
#include <cuda_bf16.h>
#include <math.h>
#include <stdint.h>

// ---------------- problem constants ----------------
#define NB 5
#define SEQ 1024
#define T 1025
#define DM 512
#define NHEAD 8
#define HD 64
#define DFF 2048
#define NL 4
#define NTOK 51
#define MLPD 256
#define CLASSES 7
#define GH 3
#define GHID 64
#define GCLS 5
#define MROWS (NB * T)
#define NBLK 41
#define GAT_GRAPHS (SEQ * 5)
#define OUT_GAT_BASE (NB * CLASSES)
#define NWIN 17
#define KV_PER_HEAD (NWIN * 4096)
#define GAT_BLOCKS (GAT_GRAPHS / 8)          // 640
#define FRAG_BLOCKS 12288
#define PRO_BLOCKS (GAT_BLOCKS + FRAG_BLOCKS + MROWS)

// ---------------- scratch ----------------
__device__ float g_h [MROWS * DM];
__device__ float g_q [MROWS * DM];
__device__ float g_t [MROWS * DM];
// fragment-packed activations (zero-init tails)
__device__ float g_hF [NBLK * 128 * DM];
__device__ float g_ffF[NBLK * 128 * DFF];
__device__ float g_aoF[NBLK * 128 * DM];
// fragment-packed (tf32-rounded) weights
__device__ float g_WqF[NL * DM * DM];
__device__ float g_WkF[NL * DM * DM];
__device__ float g_WvF[NL * DM * DM];
__device__ float g_WoF[NL * DM * DM];
__device__ float g_W1F[NL * DM * DFF];
__device__ float g_W2F[NL * DFF * DM];
// fragment-packed K / V(hi,lo)  (invalid keys stay zero from static init)
__device__ float g_kF  [NB * NHEAD * KV_PER_HEAD];
__device__ float g_vhiF[NB * NHEAD * KV_PER_HEAD];
__device__ float g_vloF[NB * NHEAD * KV_PER_HEAD];

// ---------------- helpers ----------------
__device__ __forceinline__ uint32_t ftf32(float x) {
    uint32_t r;
    asm("cvt.rna.tf32.f32 %0, %1;" : "=r"(r) : "f"(x));
    return r;
}

#define MMA_TF32(d, a, b) \
    asm volatile("mma.sync.aligned.m16n8k8.row.col.f32.tf32.tf32.f32 " \
        "{%0,%1,%2,%3}, {%4,%5,%6,%7}, {%8,%9}, {%0,%1,%2,%3};" \
        : "+f"((d)[0]), "+f"((d)[1]), "+f"((d)[2]), "+f"((d)[3]) \
        : "r"((a).x), "r"((a).y), "r"((a).z), "r"((a).w), \
          "r"((b).x), "r"((b).y))

#define MMA_TF32_P(d, a0, a1, a2, a3, b) \
    asm volatile("mma.sync.aligned.m16n8k8.row.col.f32.tf32.tf32.f32 " \
        "{%0,%1,%2,%3}, {%4,%5,%6,%7}, {%8,%9}, {%0,%1,%2,%3};" \
        : "+f"((d)[0]), "+f"((d)[1]), "+f"((d)[2]), "+f"((d)[3]) \
        : "r"(a0), "r"(a1), "r"(a2), "r"(a3), \
          "r"((b).x), "r"((b).y))

// store value into A-fragment layout (per 128-row block, width Ncols)
__device__ __forceinline__ void store_frag(float* F, int Ncols, int row, int col, float val) {
    size_t slot = (size_t)(row >> 7) * 128 * Ncols
        + (size_t)((col >> 3) * 8 + ((row & 127) >> 4)) * 128
        + ((row & 7) * 4 + (col & 3)) * 4
        + (((col & 7) >= 4) ? 2 : 0) + ((row >> 3) & 1);
    F[slot] = __uint_as_float(ftf32(val));
}

// ---------------- GAT body (one warp per graph) ----------------
__device__ void gat_body(
    int gbid,
    const float* __restrict__ x, const int* __restrict__ adj,
    const float* __restrict__ Wg, const float* __restrict__ ag,
    const float* __restrict__ Wgo, const float* __restrict__ ago,
    float* __restrict__ out)
{
    int wid = threadIdx.x >> 5, lane = threadIdx.x & 31;
    int gidx = gbid * 8 + wid;
    int s = gidx / 5, g = gidx % 5;

    float xg[5][3];
    const float* xb = x + (size_t)s * NTOK + g * 3;
    #pragma unroll
    for (int n = 0; n < 5; n++)
        #pragma unroll
        for (int c = 0; c < 3; c++)
            xg[n][c] = xb[(size_t)n * SEQ * NTOK + c];

    int av = (lane < 25) ? adj[lane] : 0;
    unsigned mb = __ballot_sync(0xffffffffu, av > 0);

    float hcat[GH][5][2];
    #pragma unroll
    for (int hd = 0; hd < GH; hd++) {
        const float* W = Wg + hd * 3 * GHID;
        float w00 = W[lane],      w01 = W[GHID + lane],      w02 = W[2 * GHID + lane];
        float w10 = W[32 + lane], w11 = W[GHID + 32 + lane], w12 = W[2 * GHID + 32 + lane];
        float a1l = ag[hd * 2 * GHID + lane];
        float a1h = ag[hd * 2 * GHID + 32 + lane];
        float a2l = ag[hd * 2 * GHID + GHID + lane];
        float a2h = ag[hd * 2 * GHID + GHID + 32 + lane];
        float hv[5][2];
        #pragma unroll
        for (int n = 0; n < 5; n++) {
            hv[n][0] = xg[n][0] * w00 + xg[n][1] * w01 + xg[n][2] * w02;
            hv[n][1] = xg[n][0] * w10 + xg[n][1] * w11 + xg[n][2] * w12;
        }
        float s1[5], s2[5];
        #pragma unroll
        for (int n = 0; n < 5; n++) {
            float p1 = hv[n][0] * a1l + hv[n][1] * a1h;
            float p2 = hv[n][0] * a2l + hv[n][1] * a2h;
            #pragma unroll
            for (int off = 16; off >= 1; off >>= 1) {
                p1 += __shfl_xor_sync(0xffffffffu, p1, off);
                p2 += __shfl_xor_sync(0xffffffffu, p2, off);
            }
            s1[n] = p1; s2[n] = p2;
        }
        float att[5][5];
        #pragma unroll
        for (int i = 0; i < 5; i++) {
            float ev[5], mx = -1e30f;
            #pragma unroll
            for (int j = 0; j < 5; j++) {
                if ((mb >> (i * 5 + j)) & 1) {
                    float e = s1[i] + s2[j];
                    e = e > 0.f ? e : 0.2f * e;
                    ev[j] = e;
                    mx = fmaxf(mx, e);
                } else ev[j] = -1e30f;
            }
            float sum = 0.f;
            #pragma unroll
            for (int j = 0; j < 5; j++) {
                float p = ((mb >> (i * 5 + j)) & 1) ? __expf(ev[j] - mx) : 0.f;
                att[i][j] = p; sum += p;
            }
            float inv = 1.f / sum;
            #pragma unroll
            for (int j = 0; j < 5; j++) att[i][j] *= inv;
        }
        #pragma unroll
        for (int n = 0; n < 5; n++) {
            float o0 = 0.f, o1 = 0.f;
            #pragma unroll
            for (int j = 0; j < 5; j++) {
                o0 += att[n][j] * hv[j][0];
                o1 += att[n][j] * hv[j][1];
            }
            hcat[hd][n][0] = o0 > 0.f ? o0 : expm1f(o0);
            hcat[hd][n][1] = o1 > 0.f ? o1 : expm1f(o1);
        }
    }

    float wg0[GH][GCLS], wg1[GH][GCLS];
    #pragma unroll
    for (int hd = 0; hd < GH; hd++)
        #pragma unroll
        for (int m = 0; m < GCLS; m++) {
            wg0[hd][m] = Wgo[(hd * GHID + lane) * GCLS + m];
            wg1[hd][m] = Wgo[(hd * GHID + 32 + lane) * GCLS + m];
        }
    float h2[5][5];
    #pragma unroll
    for (int n = 0; n < 5; n++)
        #pragma unroll
        for (int m = 0; m < 5; m++) {
            float acc = 0.f;
            #pragma unroll
            for (int hd = 0; hd < GH; hd++)
                acc += hcat[hd][n][0] * wg0[hd][m] + hcat[hd][n][1] * wg1[hd][m];
            #pragma unroll
            for (int off = 16; off >= 1; off >>= 1)
                acc += __shfl_xor_sync(0xffffffffu, acc, off);
            h2[n][m] = acc;
        }

    float s1o[5], s2o[5];
    #pragma unroll
    for (int n = 0; n < 5; n++) {
        float a1 = 0.f, a2 = 0.f;
        #pragma unroll
        for (int m = 0; m < 5; m++) {
            a1 += h2[n][m] * ago[m];
            a2 += h2[n][m] * ago[GCLS + m];
        }
        s1o[n] = a1; s2o[n] = a2;
    }
    float att2[5][5];
    #pragma unroll
    for (int i = 0; i < 5; i++) {
        float ev[5], mx = -1e30f;
        #pragma unroll
        for (int j = 0; j < 5; j++) {
            if ((mb >> (i * 5 + j)) & 1) {
                float e = s1o[i] + s2o[j];
                e = e > 0.f ? e : 0.2f * e;
                ev[j] = e;
                mx = fmaxf(mx, e);
            } else ev[j] = -1e30f;
        }
        float sum = 0.f;
        #pragma unroll
        for (int j = 0; j < 5; j++) {
            float p = ((mb >> (i * 5 + j)) & 1) ? __expf(ev[j] - mx) : 0.f;
            att2[i][j] = p; sum += p;
        }
        float inv = 1.f / sum;
        #pragma unroll
        for (int j = 0; j < 5; j++) att2[i][j] *= inv;
    }
    float o2[5][5];
    #pragma unroll
    for (int n = 0; n < 5; n++)
        #pragma unroll
        for (int m = 0; m < 5; m++) {
            float o = 0.f;
            #pragma unroll
            for (int j = 0; j < 5; j++) o += att2[n][j] * h2[j][m];
            o2[n][m] = o > 0.f ? o : expm1f(o);
        }
    if (lane < 25) {
        int n = lane / 5;
        float mx = -1e30f;
        #pragma unroll
        for (int m = 0; m < 5; m++) mx = fmaxf(mx, o2[n][m]);
        float sum = 0.f;
        #pragma unroll
        for (int m = 0; m < 5; m++) sum += __expf(o2[n][m] - mx);
        float lse = mx + logf(sum);
        out[OUT_GAT_BASE + (size_t)gidx * 25 + lane] = o2[n][lane % 5] - lse;
    }
}

// ---------------- fused prologue: gat + weight frag pack + encoder ----------------
__global__ __launch_bounds__(256) void prologue_kernel(
    const float* __restrict__ x, const int* __restrict__ adj,
    const float* __restrict__ W_enc, const float* __restrict__ b_enc,
    const float* __restrict__ cls_tok, const float* __restrict__ pos_emb,
    float* __restrict__ h, float* __restrict__ hF,
    const float* __restrict__ Wq, const float* __restrict__ Wk,
    const float* __restrict__ Wv, const float* __restrict__ Wo,
    const float* __restrict__ W1, const float* __restrict__ W2,
    float* __restrict__ WqF, float* __restrict__ WkF,
    float* __restrict__ WvF, float* __restrict__ WoF,
    float* __restrict__ W1F, float* __restrict__ W2F,
    const float* __restrict__ Wg, const float* __restrict__ ag,
    const float* __restrict__ Wgo, const float* __restrict__ ago,
    float* __restrict__ out)
{
    __shared__ float t[32][33];
    __shared__ float xs[NTOK];
    int bid = blockIdx.x;

    if (bid < GAT_BLOCKS) {
        gat_body(bid, x, adj, Wg, ag, Wgo, ago, out);
        return;
    }
    bid -= GAT_BLOCKS;

    if (bid < FRAG_BLOCKS) {
        // ---- weight -> B-fragment packing ----
        const float* W; float* Wf; int K, N, rel, nx;
        if (bid < 4096) {
            int job = bid >> 10; rel = bid & 1023;
            K = DM; N = DM; nx = 16;
            if (job == 0)      { W = Wq; Wf = WqF; }
            else if (job == 1) { W = Wk; Wf = WkF; }
            else if (job == 2) { W = Wv; Wf = WvF; }
            else               { W = Wo; Wf = WoF; }
        } else if (bid < 8192) {
            rel = bid - 4096; K = DM; N = DFF; nx = 64;
            W = W1; Wf = W1F;
        } else {
            rel = bid - 8192; K = DFF; N = DM; nx = 16;
            W = W2; Wf = W2F;
        }
        int ny = K >> 5;
        int per = nx * ny;
        int l = rel / per, r2 = rel % per;
        int n0 = (r2 % nx) * 32, k0 = (r2 / nx) * 32;
        const float* w = W + (size_t)l * K * N;
        float* o = Wf + (size_t)l * K * N;
        int tx = threadIdx.x & 31, ty = threadIdx.x >> 5;
        #pragma unroll
        for (int i = 0; i < 32; i += 8)
            t[ty + i][tx] = w[(size_t)(k0 + ty + i) * N + n0 + tx];
        __syncthreads();
        int Kt = K >> 3;
        #pragma unroll
        for (int it = 0; it < 4; it++) {
            int w2 = threadIdx.x + it * 256;
            int group = w2 >> 6, within = w2 & 63;
            int ktl = group & 3, ntl = group >> 2;
            int lane = within >> 1, r = within & 1;
            int kk = ktl * 8 + (lane & 3) + r * 4;
            int nn = ntl * 8 + (lane >> 2);
            o[((size_t)((n0 >> 3) + ntl) * Kt + (k0 >> 3) + ktl) * 64 + within]
                = __uint_as_float(ftf32(t[kk][nn]));
        }
        return;
    }
    bid -= FRAG_BLOCKS;

    // ---- encoder row (256 threads) ----
    {
        int row = bid;
        int b = row / T, tt = row % T;
        int tid = threadIdx.x;
        float* hr = h + (size_t)row * DM;
        if (tt == 0) {
            for (int d = tid; d < DM; d += 256) {
                float val = cls_tok[d] + pos_emb[d];
                hr[d] = val;
                store_frag(hF, DM, row, d, val);
            }
            return;
        }
        if (tid < NTOK) xs[tid] = x[(size_t)b * SEQ * NTOK + (size_t)(tt - 1) * NTOK + tid];
        __syncthreads();
        for (int d = tid; d < DM; d += 256) {
            float acc = b_enc[d] + pos_emb[(size_t)tt * DM + d];
            #pragma unroll 17
            for (int kk = 0; kk < NTOK; kk++)
                acc += xs[kk] * W_enc[kk * DM + d];
            hr[d] = acc;
            store_frag(hF, DM, row, d, acc);
        }
    }
}

// ---------------- frag-A GEMM: 128x64 CTA tile, 64x16 warp tile ----------------
__device__ __forceinline__ void mma_gemm_fA_body(
    const float* __restrict__ Af, const float* __restrict__ Bf,
    const float* __restrict__ bias, float* __restrict__ C,
    float* __restrict__ Cf, int M, int N, int K, int relu)
{
    int tid = threadIdx.x;
    int w = tid >> 5, lane = tid & 31;
    int bm = blockIdx.y * 128, bn = blockIdx.x * 64;
    int wm = (w & 1) * 64, wn = (w >> 1) * 16;
    int Kt = K >> 3;
    int nt0 = (bn + wn) >> 3;
    int mtw = wm >> 4;
    const float* Ab = Af + (size_t)blockIdx.y * 128 * K;

    float d[4][2][4];
    #pragma unroll
    for (int i = 0; i < 4; i++)
        #pragma unroll
        for (int j = 0; j < 2; j++)
            #pragma unroll
            for (int e = 0; e < 4; e++) d[i][j][e] = 0.f;

    uint4 ac[4];
    uint2 bc[2], bnx[2];
    #pragma unroll
    for (int i = 0; i < 4; i++)
        ac[i] = *(const uint4*)(Ab + ((mtw + i) * 32 + lane) * 4);
    #pragma unroll
    for (int j = 0; j < 2; j++)
        bc[j] = *(const uint2*)(Bf + ((size_t)(nt0 + j) * Kt) * 64 + lane * 2);

    for (int ktg = 0; ktg < Kt; ktg++) {
        if (ktg + 1 < Kt) {
            #pragma unroll
            for (int j = 0; j < 2; j++)
                bnx[j] = *(const uint2*)(Bf + ((size_t)(nt0 + j) * Kt + ktg + 1) * 64 + lane * 2);
        }
        #pragma unroll
        for (int i = 0; i < 4; i++)
            #pragma unroll
            for (int j = 0; j < 2; j++)
                MMA_TF32(d[i][j], ac[i], bc[j]);
        if (ktg + 1 < Kt) {
            #pragma unroll
            for (int i = 0; i < 4; i++)
                ac[i] = *(const uint4*)(Ab + (((ktg + 1) * 8 + mtw + i) * 32 + lane) * 4);
            #pragma unroll
            for (int j = 0; j < 2; j++) bc[j] = bnx[j];
        }
    }

    int g = lane >> 2, t2 = (lane & 3) << 1;
    if (Cf) {
        size_t cb = (size_t)blockIdx.y * 128 * N;
        #pragma unroll
        for (int i = 0; i < 4; i++)
            #pragma unroll
            for (int hh = 0; hh < 2; hh++) {
                int rloc = wm + i * 16 + g + hh * 8;
                #pragma unroll
                for (int j = 0; j < 2; j++)
                    #pragma unroll
                    for (int e = 0; e < 2; e++) {
                        int col = bn + wn + j * 8 + t2 + e;
                        float val = d[i][j][hh * 2 + e] + bias[col];
                        if (relu) val = fmaxf(val, 0.f);
                        size_t slot = cb + (size_t)((col >> 3) * 8 + (rloc >> 4)) * 128
                                      + ((rloc & 7) * 4 + (col & 3)) * 4
                                      + (((col & 7) >= 4) ? 2 : 0) + hh;
                        Cf[slot] = __uint_as_float(ftf32(val));
                    }
            }
    } else {
        #pragma unroll
        for (int i = 0; i < 4; i++) {
            #pragma unroll
            for (int hh = 0; hh < 2; hh++) {
                int row = bm + wm + i * 16 + g + hh * 8;
                if (row >= M) continue;
                #pragma unroll
                for (int j = 0; j < 2; j++) {
                    int col = bn + wn + j * 8 + t2;
                    float2 bb = *(const float2*)(bias + col);
                    float2 r;
                    r.x = d[i][j][hh * 2 + 0] + bb.x;
                    r.y = d[i][j][hh * 2 + 1] + bb.y;
                    if (relu) { r.x = fmaxf(r.x, 0.f); r.y = fmaxf(r.y, 0.f); }
                    *(float2*)(C + (size_t)row * N + col) = r;
                }
            }
        }
    }
}

__global__ __launch_bounds__(256) void mma_gemm_fA(
    const float* __restrict__ Af, const float* __restrict__ Bf,
    const float* __restrict__ bias, float* __restrict__ C,
    float* __restrict__ Cf, int M, int N, int K, int relu)
{
    mma_gemm_fA_body(Af, Bf, bias, C, Cf, M, N, K, relu);
}

// ---------------- qkv GEMM: Q -> row-major, K/V -> KV fragment layouts ----------------
__global__ __launch_bounds__(256) void mma_gemm_qkv_fA(
    const float* __restrict__ Af,
    const float* __restrict__ WqF, const float* __restrict__ WkF, const float* __restrict__ WvF,
    const float* __restrict__ bq, const float* __restrict__ bk, const float* __restrict__ bv,
    float* __restrict__ q,
    float* __restrict__ kF, float* __restrict__ vhiF, float* __restrict__ vloF)
{
    const float* Bf; const float* bias;
    if (blockIdx.z == 0)      { Bf = WqF; bias = bq; }
    else if (blockIdx.z == 1) { Bf = WkF; bias = bk; }
    else                      { Bf = WvF; bias = bv; }

    int tid = threadIdx.x;
    int w = tid >> 5, lane = tid & 31;
    int bm = blockIdx.y * 128, bn = blockIdx.x * 64;
    int wm = (w & 1) * 64, wn = (w >> 1) * 16;
    int Kt = DM >> 3;
    int nt0 = (bn + wn) >> 3;
    int mtw = wm >> 4;
    const float* Ab = Af + (size_t)blockIdx.y * 128 * DM;

    float d[4][2][4];
    #pragma unroll
    for (int i = 0; i < 4; i++)
        #pragma unroll
        for (int j = 0; j < 2; j++)
            #pragma unroll
            for (int e = 0; e < 4; e++) d[i][j][e] = 0.f;

    uint4 ac[4];
    uint2 bc[2], bnx[2];
    #pragma unroll
    for (int i = 0; i < 4; i++)
        ac[i] = *(const uint4*)(Ab + ((mtw + i) * 32 + lane) * 4);
    #pragma unroll
    for (int j = 0; j < 2; j++)
        bc[j] = *(const uint2*)(Bf + ((size_t)(nt0 + j) * Kt) * 64 + lane * 2);

    for (int ktg = 0; ktg < Kt; ktg++) {
        if (ktg + 1 < Kt) {
            #pragma unroll
            for (int j = 0; j < 2; j++)
                bnx[j] = *(const uint2*)(Bf + ((size_t)(nt0 + j) * Kt + ktg + 1) * 64 + lane * 2);
        }
        #pragma unroll
        for (int i = 0; i < 4; i++)
            #pragma unroll
            for (int j = 0; j < 2; j++)
                MMA_TF32(d[i][j], ac[i], bc[j]);
        if (ktg + 1 < Kt) {
            #pragma unroll
            for (int i = 0; i < 4; i++)
                ac[i] = *(const uint4*)(Ab + (((ktg + 1) * 8 + mtw + i) * 32 + lane) * 4);
            #pragma unroll
            for (int j = 0; j < 2; j++) bc[j] = bnx[j];
        }
    }

    int g = lane >> 2, t2 = (lane & 3) << 1;
    if (blockIdx.z == 0) {
        #pragma unroll
        for (int i = 0; i < 4; i++) {
            #pragma unroll
            for (int hh = 0; hh < 2; hh++) {
                int row = bm + wm + i * 16 + g + hh * 8;
                if (row >= MROWS) continue;
                #pragma unroll
                for (int j = 0; j < 2; j++) {
                    int col = bn + wn + j * 8 + t2;
                    float2 bb = *(const float2*)(bias + col);
                    float2 r;
                    r.x = d[i][j][hh * 2 + 0] + bb.x;
                    r.y = d[i][j][hh * 2 + 1] + bb.y;
                    *(float2*)(q + (size_t)row * DM + col) = r;
                }
            }
        }
    } else {
        int isK = (blockIdx.z == 1);
        #pragma unroll
        for (int i = 0; i < 4; i++) {
            #pragma unroll
            for (int hh = 0; hh < 2; hh++) {
                int row = bm + wm + i * 16 + g + hh * 8;
                if (row >= MROWS) continue;
                int b = row / T, t = row % T;
                int win = t >> 6, key = t & 63;
                #pragma unroll
                for (int j = 0; j < 2; j++) {
                    #pragma unroll
                    for (int e = 0; e < 2; e++) {
                        int col = bn + wn + j * 8 + t2 + e;
                        float val = d[i][j][hh * 2 + e] + bias[col];
                        int head = col >> 6, dd = col & 63;
                        size_t base = (((size_t)(b * NHEAD + head) * NWIN + win)) * 4096;
                        if (isK) {
                            kF[base + ((dd >> 3) * 8 + (key >> 3)) * 64
                               + ((key & 7) * 4 + (dd & 3)) * 2 + ((dd & 7) >> 2)]
                                = __uint_as_float(ftf32(val));
                        } else {
                            uint32_t hb = ftf32(val);
                            float hf = __uint_as_float(hb);
                            uint32_t lb = ftf32(val - hf);
                            size_t a2 = base + ((key >> 3) * 8 + (dd >> 3)) * 64
                                        + ((dd & 7) * 4 + (key & 3)) * 2 + ((key & 7) >> 2);
                            vhiF[a2] = __uint_as_float(hb);
                            vloF[a2] = __uint_as_float(lb);
                        }
                    }
                }
            }
        }
    }
}

// ---------------- tf32 mma.sync flash attention -> frag output ----------------
#define ATT_SMEM 65536

__global__ __launch_bounds__(256) void attn_mma_kernel(
    const float* __restrict__ q,
    const float* __restrict__ kF, const float* __restrict__ vhiF,
    const float* __restrict__ vloF, float* __restrict__ aoF)
{
    extern __shared__ float as_[];
    float* kp  = as_;
    float* vhi = as_ + 8192;
    float* vlo = as_ + 12288;

    int tid = threadIdx.x;
    int w = tid >> 5, lane = tid & 31;
    int g = lane >> 2, t = lane & 3;
    int qb = blockIdx.x * 128;
    int head = blockIdx.y, b = blockIdx.z;
    int bh = b * NHEAD + head;
    const float* qp = q + (size_t)b * T * DM + head * HD;
    const float* kFb = kF   + (size_t)bh * KV_PER_HEAD;
    const float* vhb = vhiF + (size_t)bh * KV_PER_HEAD;
    const float* vlb = vloF + (size_t)bh * KV_PER_HEAD;

    int r0 = qb + w * 16 + g;
    int r1 = r0 + 8;
    uint32_t aq[8][4];
    #pragma unroll
    for (int kk = 0; kk < 8; kk++) {
        int d0 = kk * 8 + t, d1 = d0 + 4;
        float q00 = 0.f, q01 = 0.f, q10 = 0.f, q11 = 0.f;
        if (r0 < T) { q00 = qp[(size_t)r0 * DM + d0]; q01 = qp[(size_t)r0 * DM + d1]; }
        if (r1 < T) { q10 = qp[(size_t)r1 * DM + d0]; q11 = qp[(size_t)r1 * DM + d1]; }
        aq[kk][0] = ftf32(q00 * 0.125f);
        aq[kk][1] = ftf32(q10 * 0.125f);
        aq[kk][2] = ftf32(q01 * 0.125f);
        aq[kk][3] = ftf32(q11 * 0.125f);
    }

    float oc[8][4];
    #pragma unroll
    for (int j = 0; j < 8; j++)
        #pragma unroll
        for (int e = 0; e < 4; e++) oc[j][e] = 0.f;
    float m0 = -1e30f, m1 = -1e30f, l0 = 0.f, l1 = 0.f;

    for (int win = 0; win < NWIN; win++) {
        int kb = win * 64;
        __syncthreads();
        {
            const float4* ks = (const float4*)(kFb + (size_t)win * 4096);
            const float4* hs = (const float4*)(vhb + (size_t)win * 4096);
            const float4* ls = (const float4*)(vlb + (size_t)win * 4096);
            float4* kd = (float4*)kp;
            float4* hd = (float4*)vhi;
            float4* ld = (float4*)vlo;
            #pragma unroll
            for (int i = 0; i < 4; i++) {
                int idx = tid + i * 256;
                kd[idx] = ks[idx];
                hd[idx] = hs[idx];
                ld[idx] = ls[idx];
            }
        }
        __syncthreads();

        float sc[8][4];
        #pragma unroll
        for (int j = 0; j < 8; j++)
            #pragma unroll
            for (int e = 0; e < 4; e++) sc[j][e] = 0.f;
        #pragma unroll
        for (int kk = 0; kk < 8; kk++) {
            #pragma unroll
            for (int j = 0; j < 8; j++) {
                uint2 bf = *(const uint2*)&kp[(kk * 8 + j) * 64 + lane * 2];
                MMA_TF32_P(sc[j], aq[kk][0], aq[kk][1], aq[kk][2], aq[kk][3], bf);
            }
        }
        __syncthreads();

        int rem = T - kb;
        if (rem < 64) {
            #pragma unroll
            for (int j = 0; j < 8; j++) {
                int c0 = j * 8 + t * 2, c1 = c0 + 1;
                if (c0 >= rem) { sc[j][0] = -1e30f; sc[j][2] = -1e30f; }
                if (c1 >= rem) { sc[j][1] = -1e30f; sc[j][3] = -1e30f; }
            }
        }
        float mx0 = -1e30f, mx1 = -1e30f;
        #pragma unroll
        for (int j = 0; j < 8; j++) {
            mx0 = fmaxf(mx0, fmaxf(sc[j][0], sc[j][1]));
            mx1 = fmaxf(mx1, fmaxf(sc[j][2], sc[j][3]));
        }
        mx0 = fmaxf(mx0, __shfl_xor_sync(0xffffffffu, mx0, 1));
        mx0 = fmaxf(mx0, __shfl_xor_sync(0xffffffffu, mx0, 2));
        mx1 = fmaxf(mx1, __shfl_xor_sync(0xffffffffu, mx1, 1));
        mx1 = fmaxf(mx1, __shfl_xor_sync(0xffffffffu, mx1, 2));
        float mn0 = fmaxf(m0, mx0), mn1 = fmaxf(m1, mx1);
        float corr0 = __expf(m0 - mn0), corr1 = __expf(m1 - mn1);
        m0 = mn0; m1 = mn1;
        float sum0 = 0.f, sum1 = 0.f;
        #pragma unroll
        for (int j = 0; j < 8; j++) {
            sc[j][0] = __expf(sc[j][0] - mn0); sum0 += sc[j][0];
            sc[j][1] = __expf(sc[j][1] - mn0); sum0 += sc[j][1];
            sc[j][2] = __expf(sc[j][2] - mn1); sum1 += sc[j][2];
            sc[j][3] = __expf(sc[j][3] - mn1); sum1 += sc[j][3];
        }
        sum0 += __shfl_xor_sync(0xffffffffu, sum0, 1);
        sum0 += __shfl_xor_sync(0xffffffffu, sum0, 2);
        sum1 += __shfl_xor_sync(0xffffffffu, sum1, 1);
        sum1 += __shfl_xor_sync(0xffffffffu, sum1, 2);
        l0 = l0 * corr0 + sum0;
        l1 = l1 * corr1 + sum1;
        #pragma unroll
        for (int j = 0; j < 8; j++) {
            oc[j][0] *= corr0; oc[j][1] *= corr0;
            oc[j][2] *= corr1; oc[j][3] *= corr1;
        }

        {
            float* pb = kp + w * 1024;
            #pragma unroll
            for (int j = 0; j < 8; j++) {
                #pragma unroll
                for (int e = 0; e < 2; e++) {
                    int kcol = t * 2 + e;
                    int base = j * 128 + (g * 4 + (kcol & 3)) * 4 + ((kcol >= 4) ? 2 : 0);
                    pb[base + 0] = __uint_as_float(ftf32(sc[j][e]));
                    pb[base + 1] = __uint_as_float(ftf32(sc[j][2 + e]));
                }
            }
        }
        __syncwarp();

        const float* pb = kp + w * 1024;
        #pragma unroll
        for (int kk = 0; kk < 8; kk++) {
            uint4 pf = *(const uint4*)&pb[kk * 128 + lane * 4];
            #pragma unroll
            for (int j = 0; j < 8; j++) {
                uint2 bh2 = *(const uint2*)&vhi[(kk * 8 + j) * 64 + lane * 2];
                MMA_TF32(oc[j], pf, bh2);
                uint2 bl2 = *(const uint2*)&vlo[(kk * 8 + j) * 64 + lane * 2];
                MMA_TF32(oc[j], pf, bl2);
            }
        }
    }

    float inv0 = 1.f / l0, inv1 = 1.f / l1;
    int gr0 = b * T + r0, gr1 = b * T + r1;
    #pragma unroll
    for (int j = 0; j < 8; j++) {
        int c0 = head * HD + j * 8 + t * 2;
        if (r0 < T) {
            store_frag(aoF, DM, gr0, c0 + 0, oc[j][0] * inv0);
            store_frag(aoF, DM, gr0, c0 + 1, oc[j][1] * inv0);
        }
        if (r1 < T) {
            store_frag(aoF, DM, gr1, c0 + 0, oc[j][2] * inv1);
            store_frag(aoF, DM, gr1, c0 + 1, oc[j][3] * inv1);
        }
    }
}

// ---------------- residual add + layernorm (round-13 scalar form) ----------------
__global__ void add_ln_kernel(float* __restrict__ h, const float* __restrict__ f,
                              const float* __restrict__ gamma, const float* __restrict__ beta,
                              float* __restrict__ hF)
{
    int row = blockIdx.x;
    int tid = threadIdx.x;  // 128
    float* hr = h + (size_t)row * DM;
    const float* fr = f + (size_t)row * DM;
    float v[4];
    float s = 0.f;
    #pragma unroll
    for (int i = 0; i < 4; i++) {
        v[i] = hr[tid + 128 * i] + fr[tid + 128 * i];
        s += v[i];
    }
    __shared__ float sm2[4];
    int lane = tid & 31, warp = tid >> 5;
    #pragma unroll
    for (int off = 16; off >= 1; off >>= 1) s += __shfl_xor_sync(0xffffffffu, s, off);
    if (lane == 0) sm2[warp] = s;
    __syncthreads();
    float mean = (sm2[0] + sm2[1] + sm2[2] + sm2[3]) * (1.f / DM);
    float vs = 0.f;
    #pragma unroll
    for (int i = 0; i < 4; i++) { float d = v[i] - mean; vs += d * d; }
    __syncthreads();
    #pragma unroll
    for (int off = 16; off >= 1; off >>= 1) vs += __shfl_xor_sync(0xffffffffu, vs, off);
    if (lane == 0) sm2[warp] = vs;
    __syncthreads();
    float var = (sm2[0] + sm2[1] + sm2[2] + sm2[3]) * (1.f / DM);
    float inv = rsqrtf(var + 1e-5f);
    #pragma unroll
    for (int i = 0; i < 4; i++) {
        int d = tid + 128 * i;
        float val = (v[i] - mean) * inv * gamma[d] + beta[d];
        hr[d] = val;
        store_frag(hF, DM, row, d, val);
    }
}

// ---------------- classification head ----------------
__global__ void head_kernel(const float* __restrict__ h,
                            const float* __restrict__ Wd1, const float* __restrict__ bd1,
                            const float* __restrict__ Wd2, const float* __restrict__ bd2,
                            float* __restrict__ out)
{
    __shared__ float mid[NB][MLPD];
    int tid = threadIdx.x; // 256
    for (int b = 0; b < NB; b++) {
        const float* cls = h + (size_t)b * T * DM;
        float acc = bd1[tid];
        for (int kk = 0; kk < DM; kk++)
            acc += cls[kk] * Wd1[kk * MLPD + tid];
        mid[b][tid] = acc;
    }
    __syncthreads();
    if (tid < NB * CLASSES) {
        int b = tid / CLASSES, c = tid % CLASSES;
        float acc = bd2[c];
        for (int m = 0; m < MLPD; m++)
            acc += mid[b][m] * Wd2[m * CLASSES + c];
        out[b * CLASSES + c] = acc;
    }
}

// ---------------- host orchestration ----------------
extern "C" void kernel_launch(void* const* d_in, const int* in_sizes, int n_in,
                              void* d_out, int out_size)
{
    const float* x       = (const float*)d_in[0];
    const int*   adj     = (const int*)  d_in[1];
    const float* W_enc   = (const float*)d_in[2];
    const float* b_enc   = (const float*)d_in[3];
    const float* cls_tok = (const float*)d_in[4];
    const float* pos_emb = (const float*)d_in[5];
    const float* Wq      = (const float*)d_in[6];
    const float* bq      = (const float*)d_in[7];
    const float* Wk      = (const float*)d_in[8];
    const float* bk      = (const float*)d_in[9];
    const float* Wv      = (const float*)d_in[10];
    const float* bv      = (const float*)d_in[11];
    const float* Wo      = (const float*)d_in[12];
    const float* bo      = (const float*)d_in[13];
    const float* W1      = (const float*)d_in[14];
    const float* b1      = (const float*)d_in[15];
    const float* W2      = (const float*)d_in[16];
    const float* b2      = (const float*)d_in[17];
    const float* g1      = (const float*)d_in[18];
    const float* be1     = (const float*)d_in[19];
    const float* g2      = (const float*)d_in[20];
    const float* be2     = (const float*)d_in[21];
    const float* Wd1     = (const float*)d_in[22];
    const float* bd1     = (const float*)d_in[23];
    const float* Wd2     = (const float*)d_in[24];
    const float* bd2     = (const float*)d_in[25];
    const float* Wg      = (const float*)d_in[26];
    const float* ag      = (const float*)d_in[27];
    const float* Wgo     = (const float*)d_in[28];
    const float* ago     = (const float*)d_in[29];
    float* out = (float*)d_out;

    float *h, *q, *t;
    float *hF, *ffF, *aoF;
    float *WqF, *WkF, *WvF, *WoF, *W1F, *W2F;
    float *kF, *vhiF, *vloF;
    cudaGetSymbolAddress((void**)&h,    g_h);
    cudaGetSymbolAddress((void**)&q,    g_q);
    cudaGetSymbolAddress((void**)&t,    g_t);
    cudaGetSymbolAddress((void**)&hF,   g_hF);
    cudaGetSymbolAddress((void**)&ffF,  g_ffF);
    cudaGetSymbolAddress((void**)&aoF,  g_aoF);
    cudaGetSymbolAddress((void**)&WqF,  g_WqF);
    cudaGetSymbolAddress((void**)&WkF,  g_WkF);
    cudaGetSymbolAddress((void**)&WvF,  g_WvF);
    cudaGetSymbolAddress((void**)&WoF,  g_WoF);
    cudaGetSymbolAddress((void**)&W1F,  g_W1F);
    cudaGetSymbolAddress((void**)&W2F,  g_W2F);
    cudaGetSymbolAddress((void**)&kF,   g_kF);
    cudaGetSymbolAddress((void**)&vhiF, g_vhiF);
    cudaGetSymbolAddress((void**)&vloF, g_vloF);

    cudaFuncSetAttribute(attn_mma_kernel, cudaFuncAttributeMaxDynamicSharedMemorySize, ATT_SMEM);

    // fused prologue: GAT + weight frag packing + encoder (all independent)
    prologue_kernel<<<PRO_BLOCKS, 256>>>(
        x, adj, W_enc, b_enc, cls_tok, pos_emb, h, hF,
        Wq, Wk, Wv, Wo, W1, W2, WqF, WkF, WvF, WoF, W1F, W2F,
        Wg, ag, Wgo, ago, out);

    dim3 grid_qkv(DM / 64, NBLK, 3);
    dim3 grid_dm(DM / 64, NBLK);
    dim3 grid_ff(DFF / 64, NBLK);
    dim3 attn_grid((T + 127) / 128, NHEAD, NB);

    for (int l = 0; l < NL; l++) {
        mma_gemm_qkv_fA<<<grid_qkv, 256>>>(
            hF, WqF + (size_t)l * DM * DM, WkF + (size_t)l * DM * DM, WvF + (size_t)l * DM * DM,
            bq + l * DM, bk + l * DM, bv + l * DM, q, kF, vhiF, vloF);
        attn_mma_kernel<<<attn_grid, 256, ATT_SMEM>>>(q, kF, vhiF, vloF, aoF);
        mma_gemm_fA<<<grid_dm, 256>>>(aoF, WoF + (size_t)l * DM * DM, bo + l * DM,
                                      t, nullptr, MROWS, DM, DM, 0);
        add_ln_kernel<<<MROWS, 128>>>(h, t, g1 + l * DM, be1 + l * DM, hF);
        mma_gemm_fA<<<grid_ff, 256>>>(hF, W1F + (size_t)l * DM * DFF, b1 + l * DFF,
                                      nullptr, ffF, MROWS, DFF, DM, 1);
        mma_gemm_fA<<<grid_dm, 256>>>(ffF, W2F + (size_t)l * DFF * DM, b2 + l * DM,
                                      t, nullptr, MROWS, DM, DFF, 0);
        add_ln_kernel<<<MROWS, 128>>>(h, t, g2 + l * DM, be2 + l * DM, hF);
    }

    head_kernel<<<1, 256>>>(h, Wd1, bd1, Wd2, bd2, out);
}

// round 17
// speedup vs baseline: 1.0782x; 1.0562x over previous
#include <cuda_runtime.h>
#include <cuda_bf16.h>
#include <math.h>
#include <stdint.h>

// ---------------- problem constants ----------------
#define NB 5
#define SEQ 1024
#define T 1025
#define DM 512
#define NHEAD 8
#define HD 64
#define DFF 2048
#define NL 4
#define NTOK 51
#define MLPD 256
#define CLASSES 7
#define GH 3
#define GHID 64
#define GCLS 5
#define MROWS (NB * T)
#define NBLK 41
#define GAT_GRAPHS (SEQ * 5)
#define OUT_GAT_BASE (NB * CLASSES)
#define NWIN 17
#define KV_PER_HEAD (NWIN * 4096)
#define GAT_BLOCKS (GAT_GRAPHS / 8)          // 640
#define FRAG_BLOCKS 12288
#define PRO_BLOCKS (GAT_BLOCKS + FRAG_BLOCKS + MROWS)

// ---------------- scratch ----------------
__device__ float g_h [MROWS * DM];
__device__ float g_q [MROWS * DM];
__device__ float g_t [MROWS * DM];
// fragment-packed activations (zero-init tails)
__device__ float g_hF [NBLK * 128 * DM];
__device__ float g_ffF[NBLK * 128 * DFF];
__device__ float g_aoF[NBLK * 128 * DM];
// fragment-packed (tf32-rounded) weights
__device__ float g_WqF[NL * DM * DM];
__device__ float g_WkF[NL * DM * DM];
__device__ float g_WvF[NL * DM * DM];
__device__ float g_WoF[NL * DM * DM];
__device__ float g_W1F[NL * DM * DFF];
__device__ float g_W2F[NL * DFF * DM];
// fragment-packed K / V (invalid keys stay zero from static init)
__device__ float g_kF[NB * NHEAD * KV_PER_HEAD];
__device__ float g_vF[NB * NHEAD * KV_PER_HEAD];

// ---------------- helpers ----------------
__device__ __forceinline__ uint32_t ftf32(float x) {
    uint32_t r;
    asm("cvt.rna.tf32.f32 %0, %1;" : "=r"(r) : "f"(x));
    return r;
}

#define MMA_TF32(d, a, b) \
    asm volatile("mma.sync.aligned.m16n8k8.row.col.f32.tf32.tf32.f32 " \
        "{%0,%1,%2,%3}, {%4,%5,%6,%7}, {%8,%9}, {%0,%1,%2,%3};" \
        : "+f"((d)[0]), "+f"((d)[1]), "+f"((d)[2]), "+f"((d)[3]) \
        : "r"((a).x), "r"((a).y), "r"((a).z), "r"((a).w), \
          "r"((b).x), "r"((b).y))

#define MMA_TF32_P(d, a0, a1, a2, a3, b) \
    asm volatile("mma.sync.aligned.m16n8k8.row.col.f32.tf32.tf32.f32 " \
        "{%0,%1,%2,%3}, {%4,%5,%6,%7}, {%8,%9}, {%0,%1,%2,%3};" \
        : "+f"((d)[0]), "+f"((d)[1]), "+f"((d)[2]), "+f"((d)[3]) \
        : "r"(a0), "r"(a1), "r"(a2), "r"(a3), \
          "r"((b).x), "r"((b).y))

// store value into A-fragment layout (per 128-row block, width Ncols)
__device__ __forceinline__ void store_frag(float* F, int Ncols, int row, int col, float val) {
    size_t slot = (size_t)(row >> 7) * 128 * Ncols
        + (size_t)((col >> 3) * 8 + ((row & 127) >> 4)) * 128
        + ((row & 7) * 4 + (col & 3)) * 4
        + (((col & 7) >= 4) ? 2 : 0) + ((row >> 3) & 1);
    F[slot] = __uint_as_float(ftf32(val));
}

// ---------------- GAT body (one warp per graph) ----------------
__device__ void gat_body(
    int gbid,
    const float* __restrict__ x, const int* __restrict__ adj,
    const float* __restrict__ Wg, const float* __restrict__ ag,
    const float* __restrict__ Wgo, const float* __restrict__ ago,
    float* __restrict__ out)
{
    int wid = threadIdx.x >> 5, lane = threadIdx.x & 31;
    int gidx = gbid * 8 + wid;
    int s = gidx / 5, g = gidx % 5;

    float xg[5][3];
    const float* xb = x + (size_t)s * NTOK + g * 3;
    #pragma unroll
    for (int n = 0; n < 5; n++)
        #pragma unroll
        for (int c = 0; c < 3; c++)
            xg[n][c] = xb[(size_t)n * SEQ * NTOK + c];

    int av = (lane < 25) ? adj[lane] : 0;
    unsigned mb = __ballot_sync(0xffffffffu, av > 0);

    float hcat[GH][5][2];
    #pragma unroll
    for (int hd = 0; hd < GH; hd++) {
        const float* W = Wg + hd * 3 * GHID;
        float w00 = W[lane],      w01 = W[GHID + lane],      w02 = W[2 * GHID + lane];
        float w10 = W[32 + lane], w11 = W[GHID + 32 + lane], w12 = W[2 * GHID + 32 + lane];
        float a1l = ag[hd * 2 * GHID + lane];
        float a1h = ag[hd * 2 * GHID + 32 + lane];
        float a2l = ag[hd * 2 * GHID + GHID + lane];
        float a2h = ag[hd * 2 * GHID + GHID + 32 + lane];
        float hv[5][2];
        #pragma unroll
        for (int n = 0; n < 5; n++) {
            hv[n][0] = xg[n][0] * w00 + xg[n][1] * w01 + xg[n][2] * w02;
            hv[n][1] = xg[n][0] * w10 + xg[n][1] * w11 + xg[n][2] * w12;
        }
        float s1[5], s2[5];
        #pragma unroll
        for (int n = 0; n < 5; n++) {
            float p1 = hv[n][0] * a1l + hv[n][1] * a1h;
            float p2 = hv[n][0] * a2l + hv[n][1] * a2h;
            #pragma unroll
            for (int off = 16; off >= 1; off >>= 1) {
                p1 += __shfl_xor_sync(0xffffffffu, p1, off);
                p2 += __shfl_xor_sync(0xffffffffu, p2, off);
            }
            s1[n] = p1; s2[n] = p2;
        }
        float att[5][5];
        #pragma unroll
        for (int i = 0; i < 5; i++) {
            float ev[5], mx = -1e30f;
            #pragma unroll
            for (int j = 0; j < 5; j++) {
                if ((mb >> (i * 5 + j)) & 1) {
                    float e = s1[i] + s2[j];
                    e = e > 0.f ? e : 0.2f * e;
                    ev[j] = e;
                    mx = fmaxf(mx, e);
                } else ev[j] = -1e30f;
            }
            float sum = 0.f;
            #pragma unroll
            for (int j = 0; j < 5; j++) {
                float p = ((mb >> (i * 5 + j)) & 1) ? __expf(ev[j] - mx) : 0.f;
                att[i][j] = p; sum += p;
            }
            float inv = 1.f / sum;
            #pragma unroll
            for (int j = 0; j < 5; j++) att[i][j] *= inv;
        }
        #pragma unroll
        for (int n = 0; n < 5; n++) {
            float o0 = 0.f, o1 = 0.f;
            #pragma unroll
            for (int j = 0; j < 5; j++) {
                o0 += att[n][j] * hv[j][0];
                o1 += att[n][j] * hv[j][1];
            }
            hcat[hd][n][0] = o0 > 0.f ? o0 : expm1f(o0);
            hcat[hd][n][1] = o1 > 0.f ? o1 : expm1f(o1);
        }
    }

    float wg0[GH][GCLS], wg1[GH][GCLS];
    #pragma unroll
    for (int hd = 0; hd < GH; hd++)
        #pragma unroll
        for (int m = 0; m < GCLS; m++) {
            wg0[hd][m] = Wgo[(hd * GHID + lane) * GCLS + m];
            wg1[hd][m] = Wgo[(hd * GHID + 32 + lane) * GCLS + m];
        }
    float h2[5][5];
    #pragma unroll
    for (int n = 0; n < 5; n++)
        #pragma unroll
        for (int m = 0; m < 5; m++) {
            float acc = 0.f;
            #pragma unroll
            for (int hd = 0; hd < GH; hd++)
                acc += hcat[hd][n][0] * wg0[hd][m] + hcat[hd][n][1] * wg1[hd][m];
            #pragma unroll
            for (int off = 16; off >= 1; off >>= 1)
                acc += __shfl_xor_sync(0xffffffffu, acc, off);
            h2[n][m] = acc;
        }

    float s1o[5], s2o[5];
    #pragma unroll
    for (int n = 0; n < 5; n++) {
        float a1 = 0.f, a2 = 0.f;
        #pragma unroll
        for (int m = 0; m < 5; m++) {
            a1 += h2[n][m] * ago[m];
            a2 += h2[n][m] * ago[GCLS + m];
        }
        s1o[n] = a1; s2o[n] = a2;
    }
    float att2[5][5];
    #pragma unroll
    for (int i = 0; i < 5; i++) {
        float ev[5], mx = -1e30f;
        #pragma unroll
        for (int j = 0; j < 5; j++) {
            if ((mb >> (i * 5 + j)) & 1) {
                float e = s1o[i] + s2o[j];
                e = e > 0.f ? e : 0.2f * e;
                ev[j] = e;
                mx = fmaxf(mx, e);
            } else ev[j] = -1e30f;
        }
        float sum = 0.f;
        #pragma unroll
        for (int j = 0; j < 5; j++) {
            float p = ((mb >> (i * 5 + j)) & 1) ? __expf(ev[j] - mx) : 0.f;
            att2[i][j] = p; sum += p;
        }
        float inv = 1.f / sum;
        #pragma unroll
        for (int j = 0; j < 5; j++) att2[i][j] *= inv;
    }
    float o2[5][5];
    #pragma unroll
    for (int n = 0; n < 5; n++)
        #pragma unroll
        for (int m = 0; m < 5; m++) {
            float o = 0.f;
            #pragma unroll
            for (int j = 0; j < 5; j++) o += att2[n][j] * h2[j][m];
            o2[n][m] = o > 0.f ? o : expm1f(o);
        }
    if (lane < 25) {
        int n = lane / 5;
        float mx = -1e30f;
        #pragma unroll
        for (int m = 0; m < 5; m++) mx = fmaxf(mx, o2[n][m]);
        float sum = 0.f;
        #pragma unroll
        for (int m = 0; m < 5; m++) sum += __expf(o2[n][m] - mx);
        float lse = mx + logf(sum);
        out[OUT_GAT_BASE + (size_t)gidx * 25 + lane] = o2[n][lane % 5] - lse;
    }
}

// ---------------- fused prologue: gat + weight frag pack + encoder ----------------
__global__ __launch_bounds__(256) void prologue_kernel(
    const float* __restrict__ x, const int* __restrict__ adj,
    const float* __restrict__ W_enc, const float* __restrict__ b_enc,
    const float* __restrict__ cls_tok, const float* __restrict__ pos_emb,
    float* __restrict__ h, float* __restrict__ hF,
    const float* __restrict__ Wq, const float* __restrict__ Wk,
    const float* __restrict__ Wv, const float* __restrict__ Wo,
    const float* __restrict__ W1, const float* __restrict__ W2,
    float* __restrict__ WqF, float* __restrict__ WkF,
    float* __restrict__ WvF, float* __restrict__ WoF,
    float* __restrict__ W1F, float* __restrict__ W2F,
    const float* __restrict__ Wg, const float* __restrict__ ag,
    const float* __restrict__ Wgo, const float* __restrict__ ago,
    float* __restrict__ out)
{
    __shared__ float t[32][33];
    __shared__ float xs[NTOK];
    int bid = blockIdx.x;

    if (bid < GAT_BLOCKS) {
        gat_body(bid, x, adj, Wg, ag, Wgo, ago, out);
        return;
    }
    bid -= GAT_BLOCKS;

    if (bid < FRAG_BLOCKS) {
        const float* W; float* Wf; int K, N, rel, nx;
        if (bid < 4096) {
            int job = bid >> 10; rel = bid & 1023;
            K = DM; N = DM; nx = 16;
            if (job == 0)      { W = Wq; Wf = WqF; }
            else if (job == 1) { W = Wk; Wf = WkF; }
            else if (job == 2) { W = Wv; Wf = WvF; }
            else               { W = Wo; Wf = WoF; }
        } else if (bid < 8192) {
            rel = bid - 4096; K = DM; N = DFF; nx = 64;
            W = W1; Wf = W1F;
        } else {
            rel = bid - 8192; K = DFF; N = DM; nx = 16;
            W = W2; Wf = W2F;
        }
        int ny = K >> 5;
        int per = nx * ny;
        int l = rel / per, r2 = rel % per;
        int n0 = (r2 % nx) * 32, k0 = (r2 / nx) * 32;
        const float* w = W + (size_t)l * K * N;
        float* o = Wf + (size_t)l * K * N;
        int tx = threadIdx.x & 31, ty = threadIdx.x >> 5;
        #pragma unroll
        for (int i = 0; i < 32; i += 8)
            t[ty + i][tx] = w[(size_t)(k0 + ty + i) * N + n0 + tx];
        __syncthreads();
        int Kt = K >> 3;
        #pragma unroll
        for (int it = 0; it < 4; it++) {
            int w2 = threadIdx.x + it * 256;
            int group = w2 >> 6, within = w2 & 63;
            int ktl = group & 3, ntl = group >> 2;
            int lane = within >> 1, r = within & 1;
            int kk = ktl * 8 + (lane & 3) + r * 4;
            int nn = ntl * 8 + (lane >> 2);
            o[((size_t)((n0 >> 3) + ntl) * Kt + (k0 >> 3) + ktl) * 64 + within]
                = __uint_as_float(ftf32(t[kk][nn]));
        }
        return;
    }
    bid -= FRAG_BLOCKS;

    // ---- encoder row (256 threads) ----
    {
        int row = bid;
        int b = row / T, tt = row % T;
        int tid = threadIdx.x;
        float* hr = h + (size_t)row * DM;
        if (tt == 0) {
            for (int d = tid; d < DM; d += 256) {
                float val = cls_tok[d] + pos_emb[d];
                hr[d] = val;
                store_frag(hF, DM, row, d, val);
            }
            return;
        }
        if (tid < NTOK) xs[tid] = x[(size_t)b * SEQ * NTOK + (size_t)(tt - 1) * NTOK + tid];
        __syncthreads();
        for (int d = tid; d < DM; d += 256) {
            float acc = b_enc[d] + pos_emb[(size_t)tt * DM + d];
            #pragma unroll 17
            for (int kk = 0; kk < NTOK; kk++)
                acc += xs[kk] * W_enc[kk * DM + d];
            hr[d] = acc;
            store_frag(hF, DM, row, d, acc);
        }
    }
}

// ---------------- frag-A GEMM: 128x64 CTA tile, 64x16 warp tile ----------------
__device__ __forceinline__ void mma_gemm_fA_body(
    const float* __restrict__ Af, const float* __restrict__ Bf,
    const float* __restrict__ bias, float* __restrict__ C,
    float* __restrict__ Cf, int M, int N, int K, int relu)
{
    int tid = threadIdx.x;
    int w = tid >> 5, lane = tid & 31;
    int bm = blockIdx.y * 128, bn = blockIdx.x * 64;
    int wm = (w & 1) * 64, wn = (w >> 1) * 16;
    int Kt = K >> 3;
    int nt0 = (bn + wn) >> 3;
    int mtw = wm >> 4;
    const float* Ab = Af + (size_t)blockIdx.y * 128 * K;

    float d[4][2][4];
    #pragma unroll
    for (int i = 0; i < 4; i++)
        #pragma unroll
        for (int j = 0; j < 2; j++)
            #pragma unroll
            for (int e = 0; e < 4; e++) d[i][j][e] = 0.f;

    uint4 ac[4];
    uint2 bc[2], bnx[2];
    #pragma unroll
    for (int i = 0; i < 4; i++)
        ac[i] = *(const uint4*)(Ab + ((mtw + i) * 32 + lane) * 4);
    #pragma unroll
    for (int j = 0; j < 2; j++)
        bc[j] = *(const uint2*)(Bf + ((size_t)(nt0 + j) * Kt) * 64 + lane * 2);

    for (int ktg = 0; ktg < Kt; ktg++) {
        if (ktg + 1 < Kt) {
            #pragma unroll
            for (int j = 0; j < 2; j++)
                bnx[j] = *(const uint2*)(Bf + ((size_t)(nt0 + j) * Kt + ktg + 1) * 64 + lane * 2);
        }
        #pragma unroll
        for (int i = 0; i < 4; i++)
            #pragma unroll
            for (int j = 0; j < 2; j++)
                MMA_TF32(d[i][j], ac[i], bc[j]);
        if (ktg + 1 < Kt) {
            #pragma unroll
            for (int i = 0; i < 4; i++)
                ac[i] = *(const uint4*)(Ab + (((ktg + 1) * 8 + mtw + i) * 32 + lane) * 4);
            #pragma unroll
            for (int j = 0; j < 2; j++) bc[j] = bnx[j];
        }
    }

    int g = lane >> 2, t2 = (lane & 3) << 1;
    if (Cf) {
        size_t cb = (size_t)blockIdx.y * 128 * N;
        #pragma unroll
        for (int i = 0; i < 4; i++)
            #pragma unroll
            for (int hh = 0; hh < 2; hh++) {
                int rloc = wm + i * 16 + g + hh * 8;
                #pragma unroll
                for (int j = 0; j < 2; j++)
                    #pragma unroll
                    for (int e = 0; e < 2; e++) {
                        int col = bn + wn + j * 8 + t2 + e;
                        float val = d[i][j][hh * 2 + e] + bias[col];
                        if (relu) val = fmaxf(val, 0.f);
                        size_t slot = cb + (size_t)((col >> 3) * 8 + (rloc >> 4)) * 128
                                      + ((rloc & 7) * 4 + (col & 3)) * 4
                                      + (((col & 7) >= 4) ? 2 : 0) + hh;
                        Cf[slot] = __uint_as_float(ftf32(val));
                    }
            }
    } else {
        #pragma unroll
        for (int i = 0; i < 4; i++) {
            #pragma unroll
            for (int hh = 0; hh < 2; hh++) {
                int row = bm + wm + i * 16 + g + hh * 8;
                if (row >= M) continue;
                #pragma unroll
                for (int j = 0; j < 2; j++) {
                    int col = bn + wn + j * 8 + t2;
                    float2 bb = *(const float2*)(bias + col);
                    float2 r;
                    r.x = d[i][j][hh * 2 + 0] + bb.x;
                    r.y = d[i][j][hh * 2 + 1] + bb.y;
                    if (relu) { r.x = fmaxf(r.x, 0.f); r.y = fmaxf(r.y, 0.f); }
                    *(float2*)(C + (size_t)row * N + col) = r;
                }
            }
        }
    }
}

__global__ __launch_bounds__(256) void mma_gemm_fA(
    const float* __restrict__ Af, const float* __restrict__ Bf,
    const float* __restrict__ bias, float* __restrict__ C,
    float* __restrict__ Cf, int M, int N, int K, int relu)
{
    mma_gemm_fA_body(Af, Bf, bias, C, Cf, M, N, K, relu);
}

// ---------------- qkv GEMM: Q -> row-major, K/V -> KV fragment layouts ----------------
__global__ __launch_bounds__(256) void mma_gemm_qkv_fA(
    const float* __restrict__ Af,
    const float* __restrict__ WqF, const float* __restrict__ WkF, const float* __restrict__ WvF,
    const float* __restrict__ bq, const float* __restrict__ bk, const float* __restrict__ bv,
    float* __restrict__ q,
    float* __restrict__ kF, float* __restrict__ vF)
{
    const float* Bf; const float* bias;
    if (blockIdx.z == 0)      { Bf = WqF; bias = bq; }
    else if (blockIdx.z == 1) { Bf = WkF; bias = bk; }
    else                      { Bf = WvF; bias = bv; }

    int tid = threadIdx.x;
    int w = tid >> 5, lane = tid & 31;
    int bm = blockIdx.y * 128, bn = blockIdx.x * 64;
    int wm = (w & 1) * 64, wn = (w >> 1) * 16;
    int Kt = DM >> 3;
    int nt0 = (bn + wn) >> 3;
    int mtw = wm >> 4;
    const float* Ab = Af + (size_t)blockIdx.y * 128 * DM;

    float d[4][2][4];
    #pragma unroll
    for (int i = 0; i < 4; i++)
        #pragma unroll
        for (int j = 0; j < 2; j++)
            #pragma unroll
            for (int e = 0; e < 4; e++) d[i][j][e] = 0.f;

    uint4 ac[4];
    uint2 bc[2], bnx[2];
    #pragma unroll
    for (int i = 0; i < 4; i++)
        ac[i] = *(const uint4*)(Ab + ((mtw + i) * 32 + lane) * 4);
    #pragma unroll
    for (int j = 0; j < 2; j++)
        bc[j] = *(const uint2*)(Bf + ((size_t)(nt0 + j) * Kt) * 64 + lane * 2);

    for (int ktg = 0; ktg < Kt; ktg++) {
        if (ktg + 1 < Kt) {
            #pragma unroll
            for (int j = 0; j < 2; j++)
                bnx[j] = *(const uint2*)(Bf + ((size_t)(nt0 + j) * Kt + ktg + 1) * 64 + lane * 2);
        }
        #pragma unroll
        for (int i = 0; i < 4; i++)
            #pragma unroll
            for (int j = 0; j < 2; j++)
                MMA_TF32(d[i][j], ac[i], bc[j]);
        if (ktg + 1 < Kt) {
            #pragma unroll
            for (int i = 0; i < 4; i++)
                ac[i] = *(const uint4*)(Ab + (((ktg + 1) * 8 + mtw + i) * 32 + lane) * 4);
            #pragma unroll
            for (int j = 0; j < 2; j++) bc[j] = bnx[j];
        }
    }

    int g = lane >> 2, t2 = (lane & 3) << 1;
    if (blockIdx.z == 0) {
        #pragma unroll
        for (int i = 0; i < 4; i++) {
            #pragma unroll
            for (int hh = 0; hh < 2; hh++) {
                int row = bm + wm + i * 16 + g + hh * 8;
                if (row >= MROWS) continue;
                #pragma unroll
                for (int j = 0; j < 2; j++) {
                    int col = bn + wn + j * 8 + t2;
                    float2 bb = *(const float2*)(bias + col);
                    float2 r;
                    r.x = d[i][j][hh * 2 + 0] + bb.x;
                    r.y = d[i][j][hh * 2 + 1] + bb.y;
                    *(float2*)(q + (size_t)row * DM + col) = r;
                }
            }
        }
    } else {
        int isK = (blockIdx.z == 1);
        #pragma unroll
        for (int i = 0; i < 4; i++) {
            #pragma unroll
            for (int hh = 0; hh < 2; hh++) {
                int row = bm + wm + i * 16 + g + hh * 8;
                if (row >= MROWS) continue;
                int b = row / T, t = row % T;
                int win = t >> 6, key = t & 63;
                #pragma unroll
                for (int j = 0; j < 2; j++) {
                    #pragma unroll
                    for (int e = 0; e < 2; e++) {
                        int col = bn + wn + j * 8 + t2 + e;
                        float val = d[i][j][hh * 2 + e] + bias[col];
                        int head = col >> 6, dd = col & 63;
                        size_t base = (((size_t)(b * NHEAD + head) * NWIN + win)) * 4096;
                        if (isK) {
                            kF[base + ((dd >> 3) * 8 + (key >> 3)) * 64
                               + ((key & 7) * 4 + (dd & 3)) * 2 + ((dd & 7) >> 2)]
                                = __uint_as_float(ftf32(val));
                        } else {
                            vF[base + ((key >> 3) * 8 + (dd >> 3)) * 64
                               + ((dd & 7) * 4 + (key & 3)) * 2 + ((key & 7) >> 2)]
                                = __uint_as_float(ftf32(val));
                        }
                    }
                }
            }
        }
    }
}

// ---------------- tf32 mma.sync flash attention -> frag output ----------------
#define ATT_SMEM 49152

__global__ __launch_bounds__(256) void attn_mma_kernel(
    const float* __restrict__ q,
    const float* __restrict__ kF, const float* __restrict__ vF,
    float* __restrict__ aoF)
{
    extern __shared__ float as_[];
    float* kp = as_;            // K B-frags (4096) then P A-frags (8192 total)
    float* vs = as_ + 8192;     // V B-frags (4096)

    int tid = threadIdx.x;
    int w = tid >> 5, lane = tid & 31;
    int g = lane >> 2, t = lane & 3;
    int qb = blockIdx.x * 128;
    int head = blockIdx.y, b = blockIdx.z;
    int bh = b * NHEAD + head;
    const float* qp = q + (size_t)b * T * DM + head * HD;
    const float* kFb = kF + (size_t)bh * KV_PER_HEAD;
    const float* vFb = vF + (size_t)bh * KV_PER_HEAD;

    int r0 = qb + w * 16 + g;
    int r1 = r0 + 8;
    uint32_t aq[8][4];
    #pragma unroll
    for (int kk = 0; kk < 8; kk++) {
        int d0 = kk * 8 + t, d1 = d0 + 4;
        float q00 = 0.f, q01 = 0.f, q10 = 0.f, q11 = 0.f;
        if (r0 < T) { q00 = qp[(size_t)r0 * DM + d0]; q01 = qp[(size_t)r0 * DM + d1]; }
        if (r1 < T) { q10 = qp[(size_t)r1 * DM + d0]; q11 = qp[(size_t)r1 * DM + d1]; }
        aq[kk][0] = ftf32(q00 * 0.125f);
        aq[kk][1] = ftf32(q10 * 0.125f);
        aq[kk][2] = ftf32(q01 * 0.125f);
        aq[kk][3] = ftf32(q11 * 0.125f);
    }

    float oc[8][4];
    #pragma unroll
    for (int j = 0; j < 8; j++)
        #pragma unroll
        for (int e = 0; e < 4; e++) oc[j][e] = 0.f;
    float m0 = -1e30f, m1 = -1e30f, l0 = 0.f, l1 = 0.f;

    for (int win = 0; win < NWIN; win++) {
        int kb = win * 64;
        __syncthreads();
        {
            const float4* ks = (const float4*)(kFb + (size_t)win * 4096);
            const float4* vsrc = (const float4*)(vFb + (size_t)win * 4096);
            float4* kd = (float4*)kp;
            float4* vd = (float4*)vs;
            #pragma unroll
            for (int i = 0; i < 4; i++) {
                int idx = tid + i * 256;
                kd[idx] = ks[idx];
                vd[idx] = vsrc[idx];
            }
        }
        __syncthreads();

        float sc[8][4];
        #pragma unroll
        for (int j = 0; j < 8; j++)
            #pragma unroll
            for (int e = 0; e < 4; e++) sc[j][e] = 0.f;
        #pragma unroll
        for (int kk = 0; kk < 8; kk++) {
            #pragma unroll
            for (int j = 0; j < 8; j++) {
                uint2 bf = *(const uint2*)&kp[(kk * 8 + j) * 64 + lane * 2];
                MMA_TF32_P(sc[j], aq[kk][0], aq[kk][1], aq[kk][2], aq[kk][3], bf);
            }
        }
        __syncthreads();   // all warps done reading K before P overwrites kp

        int rem = T - kb;
        if (rem < 64) {
            #pragma unroll
            for (int j = 0; j < 8; j++) {
                int c0 = j * 8 + t * 2, c1 = c0 + 1;
                if (c0 >= rem) { sc[j][0] = -1e30f; sc[j][2] = -1e30f; }
                if (c1 >= rem) { sc[j][1] = -1e30f; sc[j][3] = -1e30f; }
            }
        }
        float mx0 = -1e30f, mx1 = -1e30f;
        #pragma unroll
        for (int j = 0; j < 8; j++) {
            mx0 = fmaxf(mx0, fmaxf(sc[j][0], sc[j][1]));
            mx1 = fmaxf(mx1, fmaxf(sc[j][2], sc[j][3]));
        }
        mx0 = fmaxf(mx0, __shfl_xor_sync(0xffffffffu, mx0, 1));
        mx0 = fmaxf(mx0, __shfl_xor_sync(0xffffffffu, mx0, 2));
        mx1 = fmaxf(mx1, __shfl_xor_sync(0xffffffffu, mx1, 1));
        mx1 = fmaxf(mx1, __shfl_xor_sync(0xffffffffu, mx1, 2));
        float mn0 = fmaxf(m0, mx0), mn1 = fmaxf(m1, mx1);
        float corr0 = __expf(m0 - mn0), corr1 = __expf(m1 - mn1);
        m0 = mn0; m1 = mn1;
        float sum0 = 0.f, sum1 = 0.f;
        #pragma unroll
        for (int j = 0; j < 8; j++) {
            sc[j][0] = __expf(sc[j][0] - mn0); sum0 += sc[j][0];
            sc[j][1] = __expf(sc[j][1] - mn0); sum0 += sc[j][1];
            sc[j][2] = __expf(sc[j][2] - mn1); sum1 += sc[j][2];
            sc[j][3] = __expf(sc[j][3] - mn1); sum1 += sc[j][3];
        }
        sum0 += __shfl_xor_sync(0xffffffffu, sum0, 1);
        sum0 += __shfl_xor_sync(0xffffffffu, sum0, 2);
        sum1 += __shfl_xor_sync(0xffffffffu, sum1, 1);
        sum1 += __shfl_xor_sync(0xffffffffu, sum1, 2);
        l0 = l0 * corr0 + sum0;
        l1 = l1 * corr1 + sum1;
        #pragma unroll
        for (int j = 0; j < 8; j++) {
            oc[j][0] *= corr0; oc[j][1] *= corr0;
            oc[j][2] *= corr1; oc[j][3] *= corr1;
        }

        {
            float* pb = kp + w * 1024;
            #pragma unroll
            for (int j = 0; j < 8; j++) {
                #pragma unroll
                for (int e = 0; e < 2; e++) {
                    int kcol = t * 2 + e;
                    int base = j * 128 + (g * 4 + (kcol & 3)) * 4 + ((kcol >= 4) ? 2 : 0);
                    pb[base + 0] = __uint_as_float(ftf32(sc[j][e]));
                    pb[base + 1] = __uint_as_float(ftf32(sc[j][2 + e]));
                }
            }
        }
        __syncwarp();

        const float* pb = kp + w * 1024;
        #pragma unroll
        for (int kk = 0; kk < 8; kk++) {
            uint4 pf = *(const uint4*)&pb[kk * 128 + lane * 4];
            #pragma unroll
            for (int j = 0; j < 8; j++) {
                uint2 bv2 = *(const uint2*)&vs[(kk * 8 + j) * 64 + lane * 2];
                MMA_TF32(oc[j], pf, bv2);
            }
        }
    }

    float inv0 = 1.f / l0, inv1 = 1.f / l1;
    int gr0 = b * T + r0, gr1 = b * T + r1;
    #pragma unroll
    for (int j = 0; j < 8; j++) {
        int c0 = head * HD + j * 8 + t * 2;
        if (r0 < T) {
            store_frag(aoF, DM, gr0, c0 + 0, oc[j][0] * inv0);
            store_frag(aoF, DM, gr0, c0 + 1, oc[j][1] * inv0);
        }
        if (r1 < T) {
            store_frag(aoF, DM, gr1, c0 + 0, oc[j][2] * inv1);
            store_frag(aoF, DM, gr1, c0 + 1, oc[j][3] * inv1);
        }
    }
}

// ---------------- residual add + layernorm (round-13 scalar form) ----------------
__global__ void add_ln_kernel(float* __restrict__ h, const float* __restrict__ f,
                              const float* __restrict__ gamma, const float* __restrict__ beta,
                              float* __restrict__ hF)
{
    int row = blockIdx.x;
    int tid = threadIdx.x;  // 128
    float* hr = h + (size_t)row * DM;
    const float* fr = f + (size_t)row * DM;
    float v[4];
    float s = 0.f;
    #pragma unroll
    for (int i = 0; i < 4; i++) {
        v[i] = hr[tid + 128 * i] + fr[tid + 128 * i];
        s += v[i];
    }
    __shared__ float sm2[4];
    int lane = tid & 31, warp = tid >> 5;
    #pragma unroll
    for (int off = 16; off >= 1; off >>= 1) s += __shfl_xor_sync(0xffffffffu, s, off);
    if (lane == 0) sm2[warp] = s;
    __syncthreads();
    float mean = (sm2[0] + sm2[1] + sm2[2] + sm2[3]) * (1.f / DM);
    float vs = 0.f;
    #pragma unroll
    for (int i = 0; i < 4; i++) { float d = v[i] - mean; vs += d * d; }
    __syncthreads();
    #pragma unroll
    for (int off = 16; off >= 1; off >>= 1) vs += __shfl_xor_sync(0xffffffffu, vs, off);
    if (lane == 0) sm2[warp] = vs;
    __syncthreads();
    float var = (sm2[0] + sm2[1] + sm2[2] + sm2[3]) * (1.f / DM);
    float inv = rsqrtf(var + 1e-5f);
    #pragma unroll
    for (int i = 0; i < 4; i++) {
        int d = tid + 128 * i;
        float val = (v[i] - mean) * inv * gamma[d] + beta[d];
        hr[d] = val;
        store_frag(hF, DM, row, d, val);
    }
}

// ---------------- classification head ----------------
__global__ void head_kernel(const float* __restrict__ h,
                            const float* __restrict__ Wd1, const float* __restrict__ bd1,
                            const float* __restrict__ Wd2, const float* __restrict__ bd2,
                            float* __restrict__ out)
{
    __shared__ float mid[NB][MLPD];
    int tid = threadIdx.x; // 256
    for (int b = 0; b < NB; b++) {
        const float* cls = h + (size_t)b * T * DM;
        float acc = bd1[tid];
        for (int kk = 0; kk < DM; kk++)
            acc += cls[kk] * Wd1[kk * MLPD + tid];
        mid[b][tid] = acc;
    }
    __syncthreads();
    if (tid < NB * CLASSES) {
        int b = tid / CLASSES, c = tid % CLASSES;
        float acc = bd2[c];
        for (int m = 0; m < MLPD; m++)
            acc += mid[b][m] * Wd2[m * CLASSES + c];
        out[b * CLASSES + c] = acc;
    }
}

// ---------------- host orchestration ----------------
extern "C" void kernel_launch(void* const* d_in, const int* in_sizes, int n_in,
                              void* d_out, int out_size)
{
    const float* x       = (const float*)d_in[0];
    const int*   adj     = (const int*)  d_in[1];
    const float* W_enc   = (const float*)d_in[2];
    const float* b_enc   = (const float*)d_in[3];
    const float* cls_tok = (const float*)d_in[4];
    const float* pos_emb = (const float*)d_in[5];
    const float* Wq      = (const float*)d_in[6];
    const float* bq      = (const float*)d_in[7];
    const float* Wk      = (const float*)d_in[8];
    const float* bk      = (const float*)d_in[9];
    const float* Wv      = (const float*)d_in[10];
    const float* bv      = (const float*)d_in[11];
    const float* Wo      = (const float*)d_in[12];
    const float* bo      = (const float*)d_in[13];
    const float* W1      = (const float*)d_in[14];
    const float* b1      = (const float*)d_in[15];
    const float* W2      = (const float*)d_in[16];
    const float* b2      = (const float*)d_in[17];
    const float* g1      = (const float*)d_in[18];
    const float* be1     = (const float*)d_in[19];
    const float* g2      = (const float*)d_in[20];
    const float* be2     = (const float*)d_in[21];
    const float* Wd1     = (const float*)d_in[22];
    const float* bd1     = (const float*)d_in[23];
    const float* Wd2     = (const float*)d_in[24];
    const float* bd2     = (const float*)d_in[25];
    const float* Wg      = (const float*)d_in[26];
    const float* ag      = (const float*)d_in[27];
    const float* Wgo     = (const float*)d_in[28];
    const float* ago     = (const float*)d_in[29];
    float* out = (float*)d_out;

    float *h, *q, *t;
    float *hF, *ffF, *aoF;
    float *WqF, *WkF, *WvF, *WoF, *W1F, *W2F;
    float *kF, *vF;
    cudaGetSymbolAddress((void**)&h,   g_h);
    cudaGetSymbolAddress((void**)&q,   g_q);
    cudaGetSymbolAddress((void**)&t,   g_t);
    cudaGetSymbolAddress((void**)&hF,  g_hF);
    cudaGetSymbolAddress((void**)&ffF, g_ffF);
    cudaGetSymbolAddress((void**)&aoF, g_aoF);
    cudaGetSymbolAddress((void**)&WqF, g_WqF);
    cudaGetSymbolAddress((void**)&WkF, g_WkF);
    cudaGetSymbolAddress((void**)&WvF, g_WvF);
    cudaGetSymbolAddress((void**)&WoF, g_WoF);
    cudaGetSymbolAddress((void**)&W1F, g_W1F);
    cudaGetSymbolAddress((void**)&W2F, g_W2F);
    cudaGetSymbolAddress((void**)&kF,  g_kF);
    cudaGetSymbolAddress((void**)&vF,  g_vF);

    cudaFuncSetAttribute(attn_mma_kernel, cudaFuncAttributeMaxDynamicSharedMemorySize, ATT_SMEM);

    prologue_kernel<<<PRO_BLOCKS, 256>>>(
        x, adj, W_enc, b_enc, cls_tok, pos_emb, h, hF,
        Wq, Wk, Wv, Wo, W1, W2, WqF, WkF, WvF, WoF, W1F, W2F,
        Wg, ag, Wgo, ago, out);

    dim3 grid_qkv(DM / 64, NBLK, 3);
    dim3 grid_dm(DM / 64, NBLK);
    dim3 grid_ff(DFF / 64, NBLK);
    dim3 attn_grid((T + 127) / 128, NHEAD, NB);

    for (int l = 0; l < NL; l++) {
        mma_gemm_qkv_fA<<<grid_qkv, 256>>>(
            hF, WqF + (size_t)l * DM * DM, WkF + (size_t)l * DM * DM, WvF + (size_t)l * DM * DM,
            bq + l * DM, bk + l * DM, bv + l * DM, q, kF, vF);
        attn_mma_kernel<<<attn_grid, 256, ATT_SMEM>>>(q, kF, vF, aoF);
        mma_gemm_fA<<<grid_dm, 256>>>(aoF, WoF + (size_t)l * DM * DM, bo + l * DM,
                                      t, nullptr, MROWS, DM, DM, 0);
        add_ln_kernel<<<MROWS, 128>>>(h, t, g1 + l * DM, be1 + l * DM, hF);
        mma_gemm_fA<<<grid_ff, 256>>>(hF, W1F + (size_t)l * DM * DFF, b1 + l * DFF,
                                      nullptr, ffF, MROWS, DFF, DM, 1);
        mma_gemm_fA<<<grid_dm, 256>>>(ffF, W2F + (size_t)l * DFF * DM, b2 + l * DM,
                                      t, nullptr, MROWS, DM, DFF, 0);
        add_ln_kernel<<<MROWS, 128>>>(h, t, g2 + l * DM, be2 + l * DM, hF);
    }

    head_kernel<<<1, 256>>>(h, Wd1, bd1, Wd2, bd2, out);
}